// round 7
// baseline (speedup 1.0000x reference)
#include <cuda_runtime.h>
#include <cstdint>

// Problem sizes (fixed)
#define B_DIM 8192
#define F_DIM 1024
#define D_DIM 8192
#define C_DIM 512
#define DQ    128   // u64 words per D-length bit-vector

// Scratch: 8.5 MB total of static device globals (zero-initialized .bss).
__device__ unsigned long long g_encp[(size_t)B_DIM * DQ]; // 8 MB packed enc bits
__device__ unsigned long long g_hvp [(size_t)C_DIM * DQ]; // 512 KB packed hv bits

// ---------------------------------------------------------------------------
// Kernel 0 (diagnostic prefill): write 4096.0f to every output element.
// If the final kernel runs, these are all overwritten. If it doesn't,
// rel_err lands at ~1.56e-2 instead of 1.0 -> tells us which stage died.
// ---------------------------------------------------------------------------
__global__ void fill_out_kernel(float* __restrict__ out, int n)
{
    int i = blockIdx.x * blockDim.x + threadIdx.x;
    if (i < n) out[i] = 4096.0f;
}

// ---------------------------------------------------------------------------
// Kernel 1: fp32 GEMM X[B,F] @ W[F,D] with fused sign-binarize + bit-pack.
// 128x128 tile, 256 threads, 8x8 per thread, BK=16. ALL scalar memory ops.
// Epilogue: signs -> smem byte tile -> packed u64 words -> g_encp.
// ---------------------------------------------------------------------------
__global__ __launch_bounds__(256)
void gemm_binpack_kernel(const float* __restrict__ X, const float* __restrict__ W)
{
    __shared__ float As[16][128];          // [k][m]  8 KB
    __shared__ float Bs[16][128];          // [k][n]  8 KB
    __shared__ unsigned char SB[128][128]; // sign tile, 16 KB

    const int tid = threadIdx.x;
    const int tx = tid & 15;   // 0..15 -> columns
    const int ty = tid >> 4;   // 0..15 -> rows
    const int bm = blockIdx.y * 128;
    const int bn = blockIdx.x * 128;

    float acc[8][8];
#pragma unroll
    for (int i = 0; i < 8; i++)
#pragma unroll
        for (int j = 0; j < 8; j++) acc[i][j] = 0.0f;

    for (int kt = 0; kt < F_DIM; kt += 16) {
        // stage A tile: 128 rows x 16 k (scalar loads)
        for (int i = tid; i < 128 * 16; i += 256) {
            int m = i >> 4;
            int k = i & 15;
            As[k][m] = X[(size_t)(bm + m) * F_DIM + kt + k];
        }
        // stage B tile: 16 k x 128 cols (scalar loads, coalesced over n)
        for (int i = tid; i < 16 * 128; i += 256) {
            int k = i >> 7;
            int n = i & 127;
            Bs[k][n] = W[(size_t)(kt + k) * D_DIM + bn + n];
        }
        __syncthreads();

#pragma unroll
        for (int kk = 0; kk < 16; kk++) {
            float a[8], b[8];
#pragma unroll
            for (int u = 0; u < 4; u++) {
                a[u]     = As[kk][ty * 4 + u];
                a[u + 4] = As[kk][64 + ty * 4 + u];
                b[u]     = Bs[kk][tx * 4 + u];
                b[u + 4] = Bs[kk][64 + tx * 4 + u];
            }
#pragma unroll
            for (int i = 0; i < 8; i++)
#pragma unroll
                for (int j = 0; j < 8; j++)
                    acc[i][j] = fmaf(a[i], b[j], acc[i][j]);
        }
        __syncthreads();
    }

    // epilogue: signs into smem byte tile
#pragma unroll
    for (int i = 0; i < 8; i++) {
        int row = (i < 4) ? (ty * 4 + i) : (64 + ty * 4 + (i - 4));
#pragma unroll
        for (int j = 0; j < 8; j++) {
            int col = (j < 4) ? (tx * 4 + j) : (64 + tx * 4 + (j - 4));
            SB[row][col] = (acc[i][j] >= 0.0f) ? 1 : 0;
        }
    }
    __syncthreads();

    // pack: 128 rows x 2 u64 words = 256 words, one per thread.
    {
        int row  = tid >> 1;
        int half = tid & 1;
        unsigned long long bits = 0ULL;
#pragma unroll
        for (int j = 0; j < 64; j++)
            bits |= (unsigned long long)(SB[row][half * 64 + j] & 1) << j;
        g_encp[(size_t)(bm + row) * DQ + (bn >> 6) + half] = bits;
    }
}

// ---------------------------------------------------------------------------
// Kernel 2: pack classes_hv floats {0.0,1.0} -> bits (scalar loads).
// One u64 word (64 floats) per thread; 65536 threads total.
// ---------------------------------------------------------------------------
__global__ void pack_hv_kernel(const float* __restrict__ HV)
{
    int w = blockIdx.x * blockDim.x + threadIdx.x;   // 0 .. C_DIM*DQ-1
    if (w >= C_DIM * DQ) return;
    int c = w >> 7;        // class row
    int q = w & 127;       // u64 word within row
    const float* base = HV + (size_t)c * D_DIM + (size_t)q * 64;
    unsigned long long bits = 0ULL;
#pragma unroll
    for (int j = 0; j < 64; j++)
        bits |= (unsigned long long)(base[j] > 0.5f ? 1 : 0) << j;
    g_hvp[w] = bits;
}

// ---------------------------------------------------------------------------
// Kernel 3: Hamming-distance "GEMM" (exact):
//   resp[b,c] = sum_q popcll(encp[b][q] ^ hvp[c][q])
// Block: 128 b-rows x 64 c-cols, 256 threads, 8x4 per thread, K-chunk 16 u64.
// OUTPUT IS float32 (the harness __output__ dtype) — values are exact small
// integers, losslessly representable.
// ---------------------------------------------------------------------------
__global__ __launch_bounds__(256)
void popc_gemm_kernel(float* __restrict__ OUT)
{
    __shared__ unsigned long long es[16][128];  // 16 KB [word][row]
    __shared__ unsigned long long hs[16][64];   //  8 KB [word][row]

    const int tid = threadIdx.x;
    const int tx = tid & 15;
    const int ty = tid >> 4;
    const int bm = blockIdx.y * 128;
    const int bn = blockIdx.x * 64;

    int acc[8][4];
#pragma unroll
    for (int i = 0; i < 8; i++)
#pragma unroll
        for (int j = 0; j < 4; j++) acc[i][j] = 0;

    for (int k0 = 0; k0 < DQ; k0 += 16) {
        for (int i = tid; i < 128 * 16; i += 256) {
            int row = i >> 4;
            int w   = i & 15;
            es[w][row] = g_encp[(size_t)(bm + row) * DQ + k0 + w];
        }
        for (int i = tid; i < 64 * 16; i += 256) {
            int row = i >> 4;
            int w   = i & 15;
            hs[w][row] = g_hvp[(size_t)(bn + row) * DQ + k0 + w];
        }
        __syncthreads();

#pragma unroll
        for (int w = 0; w < 16; w++) {
            unsigned long long h[4], e[8];
#pragma unroll
            for (int j = 0; j < 4; j++) h[j] = hs[w][tx * 4 + j];
#pragma unroll
            for (int i = 0; i < 8; i++) e[i] = es[w][ty * 8 + i];
#pragma unroll
            for (int i = 0; i < 8; i++)
#pragma unroll
                for (int j = 0; j < 4; j++)
                    acc[i][j] += __popcll(e[i] ^ h[j]);
        }
        __syncthreads();
    }

#pragma unroll
    for (int i = 0; i < 8; i++)
#pragma unroll
        for (int j = 0; j < 4; j++)
            OUT[(size_t)(bm + ty * 8 + i) * C_DIM + bn + tx * 4 + j] =
                (float)acc[i][j];
}

// ---------------------------------------------------------------------------
// Launch. Positional input mapping per metadata order: x, W, classes_hv.
// Output written as float32.
// ---------------------------------------------------------------------------
extern "C" void kernel_launch(void* const* d_in, const int* in_sizes, int n_in,
                              void* d_out, int out_size)
{
    const float* x  = (const float*)d_in[0];   // [8192, 1024]
    const float* W  = (const float*)d_in[1];   // [1024, 8192]
    const float* hv = (const float*)d_in[2];   // [512, 8192]
    float* out = (float*)d_out;                // [8192, 512] float32

    // Kernel 0: diagnostic prefill (overwritten by kernel 3 when healthy)
    fill_out_kernel<<<(out_size + 255) / 256, 256>>>(out, out_size);

    // Kernel 1: GEMM + binarize + pack
    dim3 g1(D_DIM / 128, B_DIM / 128);         // (64, 64)
    gemm_binpack_kernel<<<g1, 256>>>(x, W);

    // Kernel 2: pack hypervectors
    pack_hv_kernel<<<(C_DIM * DQ + 255) / 256, 256>>>(hv);

    // Kernel 3: Hamming popcount GEMM (float output)
    dim3 g3(C_DIM / 64, B_DIM / 128);          // (8, 64)
    popc_gemm_kernel<<<g3, 256>>>(out);
}

// round 8
// speedup vs baseline: 2.2006x; 2.2006x over previous
#include <cuda_runtime.h>
#include <cuda_bf16.h>
#include <cstdint>

// Problem sizes (fixed)
#define B_DIM 8192
#define F_DIM 1024
#define D_DIM 8192
#define C_DIM 512
#define DQ    128          // u64 words per D-length bit-vector
#define KSPLIT (3 * F_DIM) // 3072: [Xhi|Xhi|Xlo] x [Whi;Wlo;Whi]

// Static device scratch (no allocation)
__device__ unsigned long long g_encp[(size_t)B_DIM * DQ];      // 8 MB packed enc bits
__device__ unsigned long long g_hvp [(size_t)C_DIM * DQ];      // 512 KB packed hv bits
__device__ __nv_bfloat16      g_Xs[(size_t)B_DIM * KSPLIT];    // 48 MB split X
__device__ __nv_bfloat16      g_Ws[(size_t)KSPLIT * D_DIM];    // 48 MB split W

union BF2U { __nv_bfloat16 b; unsigned short u; };
__device__ __forceinline__ unsigned short bf_bits(float f) {
    BF2U t; t.b = __float2bfloat16_rn(f); return t.u;
}

// ---------------------------------------------------------------------------
// Kernel 0 (diagnostic prefill)
// ---------------------------------------------------------------------------
__global__ void fill_out_kernel(float* __restrict__ out, int n)
{
    int i = blockIdx.x * blockDim.x + threadIdx.x;
    if (i < n) out[i] = 4096.0f;
}

// ---------------------------------------------------------------------------
// Convert X[B,F] fp32 -> Xs[B,3K] bf16 as [hi | hi | lo], 4 elems per thread.
// ---------------------------------------------------------------------------
__global__ void convert_x_kernel(const float* __restrict__ X)
{
    int idx = blockIdx.x * blockDim.x + threadIdx.x;       // 0 .. B*F/4-1
    if (idx >= B_DIM * F_DIM / 4) return;
    int b = idx >> 8;                // F/4 = 256 chunks per row
    int f = (idx & 255) * 4;
    float4 v = *reinterpret_cast<const float4*>(&X[(size_t)b * F_DIM + f]);

    unsigned short h[4], l[4];
    float vv[4] = {v.x, v.y, v.z, v.w};
#pragma unroll
    for (int i = 0; i < 4; i++) {
        h[i] = bf_bits(vv[i]);
        BF2U t; t.u = h[i];
        l[i] = bf_bits(vv[i] - __bfloat162float(t.b));
    }
    uint2 hw = make_uint2((unsigned)h[0] | ((unsigned)h[1] << 16),
                          (unsigned)h[2] | ((unsigned)h[3] << 16));
    uint2 lw = make_uint2((unsigned)l[0] | ((unsigned)l[1] << 16),
                          (unsigned)l[2] | ((unsigned)l[3] << 16));
    size_t base = (size_t)b * KSPLIT;
    *reinterpret_cast<uint2*>(&g_Xs[base + f])              = hw;
    *reinterpret_cast<uint2*>(&g_Xs[base + F_DIM + f])      = hw;
    *reinterpret_cast<uint2*>(&g_Xs[base + 2 * F_DIM + f])  = lw;
}

// ---------------------------------------------------------------------------
// Convert W[F,D] fp32 -> Ws[3K,D] bf16 as [hi ; lo ; hi], 4 elems per thread.
// ---------------------------------------------------------------------------
__global__ void convert_w_kernel(const float* __restrict__ W)
{
    int idx = blockIdx.x * blockDim.x + threadIdx.x;       // 0 .. F*D/4-1
    if (idx >= F_DIM * D_DIM / 4) return;
    int f = idx >> 11;               // D/4 = 2048 chunks per row
    int d = (idx & 2047) * 4;
    float4 v = *reinterpret_cast<const float4*>(&W[(size_t)f * D_DIM + d]);

    unsigned short h[4], l[4];
    float vv[4] = {v.x, v.y, v.z, v.w};
#pragma unroll
    for (int i = 0; i < 4; i++) {
        h[i] = bf_bits(vv[i]);
        BF2U t; t.u = h[i];
        l[i] = bf_bits(vv[i] - __bfloat162float(t.b));
    }
    uint2 hw = make_uint2((unsigned)h[0] | ((unsigned)h[1] << 16),
                          (unsigned)h[2] | ((unsigned)h[3] << 16));
    uint2 lw = make_uint2((unsigned)l[0] | ((unsigned)l[1] << 16),
                          (unsigned)l[2] | ((unsigned)l[3] << 16));
    *reinterpret_cast<uint2*>(&g_Ws[(size_t)f * D_DIM + d])                    = hw;
    *reinterpret_cast<uint2*>(&g_Ws[(size_t)(F_DIM + f) * D_DIM + d])          = lw;
    *reinterpret_cast<uint2*>(&g_Ws[(size_t)(2 * F_DIM + f) * D_DIM + d])      = hw;
}

// ---------------------------------------------------------------------------
// Kernel 1: bf16 HMMA GEMM  Xs[B,3K] @ Ws[3K,D], fp32 accum, fused sign+pack.
// 128x128 tile, 256 threads (8 warps as 2x4), BK=32, mma.sync m16n8k16.
// ---------------------------------------------------------------------------
__global__ __launch_bounds__(256)
void gemm_mma_binpack_kernel()
{
    __shared__ __align__(16) __nv_bfloat16 As[128][40];   // 10 KB (pad 8)
    __shared__ __align__(16) __nv_bfloat16 Bs[32][136];   // 8.5 KB (pad 8)
    __shared__ unsigned char SB[128][128];                // 16 KB sign tile

    const int tid  = threadIdx.x;
    const int wid  = tid >> 5;
    const int lane = tid & 31;
    const int bm = blockIdx.y * 128;
    const int bn = blockIdx.x * 128;

    const int wm = (wid >> 2) * 64;   // warp m-offset (0 or 64)
    const int wn = (wid & 3) * 32;    // warp n-offset (0,32,64,96)

    float acc[4][4][4];               // [m-frag][n-frag(8col)][reg]
#pragma unroll
    for (int i = 0; i < 4; i++)
#pragma unroll
        for (int j = 0; j < 4; j++)
#pragma unroll
            for (int r = 0; r < 4; r++) acc[i][j][r] = 0.0f;

    // ldmatrix lane geometry
    const int lg = lane >> 3;         // address group 0..3
    const int lr = lane & 7;          // row within group

    for (int kt = 0; kt < KSPLIT; kt += 32) {
        // --- stage A tile 128x32 (512 uint4, 2 per thread) ---
#pragma unroll
        for (int u = 0; u < 2; u++) {
            int idx = tid + u * 256;
            int row = idx >> 2;               // 0..127
            int ch  = (idx & 3) * 8;          // 0,8,16,24
            *reinterpret_cast<uint4*>(&As[row][ch]) =
                *reinterpret_cast<const uint4*>(
                    &g_Xs[(size_t)(bm + row) * KSPLIT + kt + ch]);
        }
        // --- stage B tile 32x128 (512 uint4, 2 per thread) ---
#pragma unroll
        for (int u = 0; u < 2; u++) {
            int idx = tid + u * 256;
            int kr = idx >> 4;                // 0..31
            int ch = (idx & 15) * 8;          // 0..120
            *reinterpret_cast<uint4*>(&Bs[kr][ch]) =
                *reinterpret_cast<const uint4*>(
                    &g_Ws[(size_t)(kt + kr) * D_DIM + bn + ch]);
        }
        __syncthreads();

#pragma unroll
        for (int kk = 0; kk < 32; kk += 16) {
            // A fragments: 4 m-frags, each ldmatrix x4
            unsigned a[4][4];
#pragma unroll
            for (int i = 0; i < 4; i++) {
                int row = wm + i * 16 + lr + (lg & 1) * 8;
                int col = kk + (lg >> 1) * 8;
                unsigned addr = (unsigned)__cvta_generic_to_shared(&As[row][col]);
                asm volatile(
                    "ldmatrix.sync.aligned.m8n8.x4.shared.b16 {%0,%1,%2,%3}, [%4];"
                    : "=r"(a[i][0]), "=r"(a[i][1]), "=r"(a[i][2]), "=r"(a[i][3])
                    : "r"(addr));
            }
            // B fragments: 2 ldmatrix.trans x4 -> 4 n-frags of 8 cols
            unsigned bfr[4][2];
#pragma unroll
            for (int j = 0; j < 2; j++) {
                int krow = kk + lr + (lg & 1) * 8;
                int col  = wn + j * 16 + (lg >> 1) * 8;
                unsigned addr = (unsigned)__cvta_generic_to_shared(&Bs[krow][col]);
                unsigned r0, r1, r2, r3;
                asm volatile(
                    "ldmatrix.sync.aligned.m8n8.x4.trans.shared.b16 {%0,%1,%2,%3}, [%4];"
                    : "=r"(r0), "=r"(r1), "=r"(r2), "=r"(r3)
                    : "r"(addr));
                bfr[j * 2 + 0][0] = r0; bfr[j * 2 + 0][1] = r1;
                bfr[j * 2 + 1][0] = r2; bfr[j * 2 + 1][1] = r3;
            }
            // 16 mma per k-step
#pragma unroll
            for (int i = 0; i < 4; i++)
#pragma unroll
                for (int j = 0; j < 4; j++) {
                    asm volatile(
                        "mma.sync.aligned.m16n8k16.row.col.f32.bf16.bf16.f32 "
                        "{%0,%1,%2,%3}, {%4,%5,%6,%7}, {%8,%9}, {%0,%1,%2,%3};"
                        : "+f"(acc[i][j][0]), "+f"(acc[i][j][1]),
                          "+f"(acc[i][j][2]), "+f"(acc[i][j][3])
                        : "r"(a[i][0]), "r"(a[i][1]), "r"(a[i][2]), "r"(a[i][3]),
                          "r"(bfr[j][0]), "r"(bfr[j][1]));
                }
        }
        __syncthreads();
    }

    // --- epilogue: signs into SB ---
    const int qr = lane >> 2;        // 0..7
    const int qc = (lane & 3) * 2;   // 0,2,4,6
#pragma unroll
    for (int i = 0; i < 4; i++)
#pragma unroll
        for (int j = 0; j < 4; j++) {
            int row0 = wm + i * 16 + qr;
            int col0 = wn + j * 8 + qc;
            SB[row0][col0]         = (acc[i][j][0] >= 0.0f) ? 1 : 0;
            SB[row0][col0 + 1]     = (acc[i][j][1] >= 0.0f) ? 1 : 0;
            SB[row0 + 8][col0]     = (acc[i][j][2] >= 0.0f) ? 1 : 0;
            SB[row0 + 8][col0 + 1] = (acc[i][j][3] >= 0.0f) ? 1 : 0;
        }
    __syncthreads();

    // --- pack: 128 rows x 2 u64 words, one per thread ---
    {
        int row  = tid >> 1;
        int half = tid & 1;
        unsigned long long bits = 0ULL;
#pragma unroll
        for (int j = 0; j < 64; j++)
            bits |= (unsigned long long)(SB[row][half * 64 + j] & 1) << j;
        g_encp[(size_t)(bm + row) * DQ + (bn >> 6) + half] = bits;
    }
}

// ---------------------------------------------------------------------------
// Kernel 2: pack classes_hv floats {0.0,1.0} -> bits.
// ---------------------------------------------------------------------------
__global__ void pack_hv_kernel(const float* __restrict__ HV)
{
    int w = blockIdx.x * blockDim.x + threadIdx.x;   // 0 .. C_DIM*DQ-1
    if (w >= C_DIM * DQ) return;
    int c = w >> 7;
    int q = w & 127;
    const float* base = HV + (size_t)c * D_DIM + (size_t)q * 64;
    unsigned long long bits = 0ULL;
#pragma unroll
    for (int j = 0; j < 64; j++)
        bits |= (unsigned long long)(base[j] > 0.5f ? 1 : 0) << j;
    g_hvp[w] = bits;
}

// ---------------------------------------------------------------------------
// Kernel 3: Hamming popcount GEMM (float output; values exact small ints).
// ---------------------------------------------------------------------------
__global__ __launch_bounds__(256)
void popc_gemm_kernel(float* __restrict__ OUT)
{
    __shared__ unsigned long long es[16][128];
    __shared__ unsigned long long hs[16][64];

    const int tid = threadIdx.x;
    const int tx = tid & 15;
    const int ty = tid >> 4;
    const int bm = blockIdx.y * 128;
    const int bn = blockIdx.x * 64;

    int acc[8][4];
#pragma unroll
    for (int i = 0; i < 8; i++)
#pragma unroll
        for (int j = 0; j < 4; j++) acc[i][j] = 0;

    for (int k0 = 0; k0 < DQ; k0 += 16) {
        for (int i = tid; i < 128 * 16; i += 256) {
            int row = i >> 4;
            int w   = i & 15;
            es[w][row] = g_encp[(size_t)(bm + row) * DQ + k0 + w];
        }
        for (int i = tid; i < 64 * 16; i += 256) {
            int row = i >> 4;
            int w   = i & 15;
            hs[w][row] = g_hvp[(size_t)(bn + row) * DQ + k0 + w];
        }
        __syncthreads();

#pragma unroll
        for (int w = 0; w < 16; w++) {
            unsigned long long h[4], e[8];
#pragma unroll
            for (int j = 0; j < 4; j++) h[j] = hs[w][tx * 4 + j];
#pragma unroll
            for (int i = 0; i < 8; i++) e[i] = es[w][ty * 8 + i];
#pragma unroll
            for (int i = 0; i < 8; i++)
#pragma unroll
                for (int j = 0; j < 4; j++)
                    acc[i][j] += __popcll(e[i] ^ h[j]);
        }
        __syncthreads();
    }

#pragma unroll
    for (int i = 0; i < 8; i++)
#pragma unroll
        for (int j = 0; j < 4; j++)
            OUT[(size_t)(bm + ty * 8 + i) * C_DIM + bn + tx * 4 + j] =
                (float)acc[i][j];
}

// ---------------------------------------------------------------------------
// Launch: prefill -> convert X,W -> HMMA GEMM+pack -> pack hv -> popc GEMM.
// ---------------------------------------------------------------------------
extern "C" void kernel_launch(void* const* d_in, const int* in_sizes, int n_in,
                              void* d_out, int out_size)
{
    const float* x  = (const float*)d_in[0];   // [8192, 1024]
    const float* W  = (const float*)d_in[1];   // [1024, 8192]
    const float* hv = (const float*)d_in[2];   // [512, 8192]
    float* out = (float*)d_out;                // [8192, 512] float32

    fill_out_kernel<<<(out_size + 255) / 256, 256>>>(out, out_size);

    convert_x_kernel<<<(B_DIM * F_DIM / 4 + 255) / 256, 256>>>(x);
    convert_w_kernel<<<(F_DIM * D_DIM / 4 + 255) / 256, 256>>>(W);

    dim3 g1(D_DIM / 128, B_DIM / 128);         // (64, 64)
    gemm_mma_binpack_kernel<<<g1, 256>>>();

    pack_hv_kernel<<<(C_DIM * DQ + 255) / 256, 256>>>(hv);

    dim3 g3(C_DIM / 64, B_DIM / 128);          // (8, 64)
    popc_gemm_kernel<<<g3, 256>>>(out);
}

// round 10
// speedup vs baseline: 2.8204x; 1.2817x over previous
#include <cuda_runtime.h>
#include <cuda_bf16.h>
#include <cstdint>

// Problem sizes (fixed)
#define B_DIM 8192
#define F_DIM 1024
#define D_DIM 8192
#define C_DIM 512
#define DQ    128          // u64 words per D-length bit-vector
#define KSPLIT (3 * F_DIM) // 3072: [Xhi|Xhi|Xlo] x [Whi;Wlo;Whi]
#define NK    (KSPLIT / 32)  // 96 BK=32 steps

// Static device scratch (no allocation)
__device__ unsigned long long g_encp[(size_t)B_DIM * DQ];      // 8 MB packed enc bits
__device__ unsigned long long g_hvp [(size_t)C_DIM * DQ];      // 512 KB packed hv bits
__device__ __nv_bfloat16      g_Xs[(size_t)B_DIM * KSPLIT];    // 48 MB split X
__device__ __nv_bfloat16      g_Ws[(size_t)KSPLIT * D_DIM];    // 48 MB split W

union BF2U { __nv_bfloat16 b; unsigned short u; };
__device__ __forceinline__ unsigned short bf_bits(float f) {
    BF2U t; t.b = __float2bfloat16_rn(f); return t.u;
}

__device__ __forceinline__ void cpa16(uint32_t dst, const void* src) {
    asm volatile("cp.async.cg.shared.global [%0], [%1], 16;"
                 :: "r"(dst), "l"(src) : "memory");
}
#define CP_COMMIT() asm volatile("cp.async.commit_group;" ::: "memory")
#define CP_WAIT1()  asm volatile("cp.async.wait_group 1;"  ::: "memory")

// SMEM stage layout (bytes): A 128x40 bf16 = 10240, B 32x136 bf16 = 8704
#define A_BYTES 10240
#define STAGE_BYTES 18944
#define NSTAGE 3
#define SMEM_TOTAL (NSTAGE * STAGE_BYTES)   // 56832

// ---------------------------------------------------------------------------
// Kernel 0 (diagnostic prefill)
// ---------------------------------------------------------------------------
__global__ void fill_out_kernel(float* __restrict__ out, int n)
{
    int i = blockIdx.x * blockDim.x + threadIdx.x;
    if (i < n) out[i] = 4096.0f;
}

// ---------------------------------------------------------------------------
// Convert X[B,F] fp32 -> Xs[B,3K] bf16 as [hi | hi | lo], 4 elems per thread.
// ---------------------------------------------------------------------------
__global__ void convert_x_kernel(const float* __restrict__ X)
{
    int idx = blockIdx.x * blockDim.x + threadIdx.x;       // 0 .. B*F/4-1
    if (idx >= B_DIM * F_DIM / 4) return;
    int b = idx >> 8;                // F/4 = 256 chunks per row
    int f = (idx & 255) * 4;
    float4 v = *reinterpret_cast<const float4*>(&X[(size_t)b * F_DIM + f]);

    unsigned short h[4], l[4];
    float vv[4] = {v.x, v.y, v.z, v.w};
#pragma unroll
    for (int i = 0; i < 4; i++) {
        h[i] = bf_bits(vv[i]);
        BF2U t; t.u = h[i];
        l[i] = bf_bits(vv[i] - __bfloat162float(t.b));
    }
    uint2 hw = make_uint2((unsigned)h[0] | ((unsigned)h[1] << 16),
                          (unsigned)h[2] | ((unsigned)h[3] << 16));
    uint2 lw = make_uint2((unsigned)l[0] | ((unsigned)l[1] << 16),
                          (unsigned)l[2] | ((unsigned)l[3] << 16));
    size_t base = (size_t)b * KSPLIT;
    *reinterpret_cast<uint2*>(&g_Xs[base + f])              = hw;
    *reinterpret_cast<uint2*>(&g_Xs[base + F_DIM + f])      = hw;
    *reinterpret_cast<uint2*>(&g_Xs[base + 2 * F_DIM + f])  = lw;
}

// ---------------------------------------------------------------------------
// Convert W[F,D] fp32 -> Ws[3K,D] bf16 as [hi ; lo ; hi], 4 elems per thread.
// ---------------------------------------------------------------------------
__global__ void convert_w_kernel(const float* __restrict__ W)
{
    int idx = blockIdx.x * blockDim.x + threadIdx.x;       // 0 .. F*D/4-1
    if (idx >= F_DIM * D_DIM / 4) return;
    int f = idx >> 11;               // D/4 = 2048 chunks per row
    int d = (idx & 2047) * 4;
    float4 v = *reinterpret_cast<const float4*>(&W[(size_t)f * D_DIM + d]);

    unsigned short h[4], l[4];
    float vv[4] = {v.x, v.y, v.z, v.w};
#pragma unroll
    for (int i = 0; i < 4; i++) {
        h[i] = bf_bits(vv[i]);
        BF2U t; t.u = h[i];
        l[i] = bf_bits(vv[i] - __bfloat162float(t.b));
    }
    uint2 hw = make_uint2((unsigned)h[0] | ((unsigned)h[1] << 16),
                          (unsigned)h[2] | ((unsigned)h[3] << 16));
    uint2 lw = make_uint2((unsigned)l[0] | ((unsigned)l[1] << 16),
                          (unsigned)l[2] | ((unsigned)l[3] << 16));
    *reinterpret_cast<uint2*>(&g_Ws[(size_t)f * D_DIM + d])               = hw;
    *reinterpret_cast<uint2*>(&g_Ws[(size_t)(F_DIM + f) * D_DIM + d])     = lw;
    *reinterpret_cast<uint2*>(&g_Ws[(size_t)(2 * F_DIM + f) * D_DIM + d]) = hw;
}

// ---------------------------------------------------------------------------
// Kernel 1: bf16 HMMA GEMM  Xs[B,3K] @ Ws[3K,D], fp32 accum, fused sign+pack.
// 128x128 tile, 256 threads (8 warps as 2x4), BK=32, mma.sync m16n8k16.
// 3-stage cp.async pipeline; 2 CTAs/SM.
// ---------------------------------------------------------------------------
__global__ __launch_bounds__(256, 2)
void gemm_mma_binpack_kernel()
{
    extern __shared__ __align__(16) char smem[];

    const int tid  = threadIdx.x;
    const int wid  = tid >> 5;
    const int lane = tid & 31;
    const int bm = blockIdx.y * 128;
    const int bn = blockIdx.x * 128;

    const int wm = (wid >> 2) * 64;   // warp m-offset (0 or 64)
    const int wn = (wid & 3) * 32;    // warp n-offset (0,32,64,96)

    float acc[4][4][4];
#pragma unroll
    for (int i = 0; i < 4; i++)
#pragma unroll
        for (int j = 0; j < 4; j++)
#pragma unroll
            for (int r = 0; r < 4; r++) acc[i][j][r] = 0.0f;

    // ldmatrix lane geometry
    const int lg = lane >> 3;         // address group 0..3
    const int lr = lane & 7;          // row within group

    // cp.async per-thread geometry:
    // A stage: 128 rows x 32 k = 512 x 16B chunks; row = idx>>2, ch=(idx&3)*16B
    // B stage: 32 k x 128 n    = 512 x 16B chunks; kr  = idx>>4, ch=(idx&15)*16B
    const int a_row = tid >> 1;            // 0..127  (u adds 128.. wait: 2/thread)
    // use idx = tid + u*256
    uint32_t smem_u32_base;
    asm("{ .reg .u64 t; cvta.to.shared.u64 t, %1; cvt.u32.u64 %0, t; }"
        : "=r"(smem_u32_base) : "l"(smem));
    (void)a_row;

    auto load_stage = [&](int kt, int buf) {
        const uint32_t ab = smem_u32_base + buf * STAGE_BYTES;
        const uint32_t bb = ab + A_BYTES;
#pragma unroll
        for (int u = 0; u < 2; u++) {
            int idx = tid + u * 256;
            int row = idx >> 2;            // 0..127
            int ch  = idx & 3;             // 16B chunk in row (32 bf16 = 4 chunks)
            cpa16(ab + row * 80 + ch * 16,
                  &g_Xs[(size_t)(bm + row) * KSPLIT + kt + ch * 8]);
        }
#pragma unroll
        for (int u = 0; u < 2; u++) {
            int idx = tid + u * 256;
            int kr = idx >> 4;             // 0..31
            int ch = idx & 15;             // 16B chunk (128 bf16 = 16 chunks)
            cpa16(bb + kr * 272 + ch * 16,
                  &g_Ws[(size_t)(kt + kr) * D_DIM + bn + ch * 8]);
        }
    };

    // --- prologue: 2 stages in flight ---
    load_stage(0, 0);  CP_COMMIT();
    load_stage(32, 1); CP_COMMIT();

    for (int it = 0; it < NK; it++) {
        CP_WAIT1();
        __syncthreads();                       // stage it%3 resident for all

        if (it + 2 < NK) load_stage((it + 2) * 32, (it + 2) % 3);
        CP_COMMIT();                           // real or empty group

        const int buf = it % 3;
        __nv_bfloat16 (*As)[40] =
            reinterpret_cast<__nv_bfloat16(*)[40]>(smem + buf * STAGE_BYTES);
        __nv_bfloat16 (*Bs)[136] =
            reinterpret_cast<__nv_bfloat16(*)[136]>(smem + buf * STAGE_BYTES + A_BYTES);

#pragma unroll
        for (int kk = 0; kk < 32; kk += 16) {
            unsigned a[4][4];
#pragma unroll
            for (int i = 0; i < 4; i++) {
                int row = wm + i * 16 + lr + (lg & 1) * 8;
                int col = kk + (lg >> 1) * 8;
                unsigned addr = (unsigned)__cvta_generic_to_shared(&As[row][col]);
                asm volatile(
                    "ldmatrix.sync.aligned.m8n8.x4.shared.b16 {%0,%1,%2,%3}, [%4];"
                    : "=r"(a[i][0]), "=r"(a[i][1]), "=r"(a[i][2]), "=r"(a[i][3])
                    : "r"(addr));
            }
            unsigned bfr[4][2];
#pragma unroll
            for (int j = 0; j < 2; j++) {
                int krow = kk + lr + (lg & 1) * 8;
                int col  = wn + j * 16 + (lg >> 1) * 8;
                unsigned addr = (unsigned)__cvta_generic_to_shared(&Bs[krow][col]);
                unsigned r0, r1, r2, r3;
                asm volatile(
                    "ldmatrix.sync.aligned.m8n8.x4.trans.shared.b16 {%0,%1,%2,%3}, [%4];"
                    : "=r"(r0), "=r"(r1), "=r"(r2), "=r"(r3)
                    : "r"(addr));
                bfr[j * 2 + 0][0] = r0; bfr[j * 2 + 0][1] = r1;
                bfr[j * 2 + 1][0] = r2; bfr[j * 2 + 1][1] = r3;
            }
#pragma unroll
            for (int i = 0; i < 4; i++)
#pragma unroll
                for (int j = 0; j < 4; j++) {
                    asm volatile(
                        "mma.sync.aligned.m16n8k16.row.col.f32.bf16.bf16.f32 "
                        "{%0,%1,%2,%3}, {%4,%5,%6,%7}, {%8,%9}, {%0,%1,%2,%3};"
                        : "+f"(acc[i][j][0]), "+f"(acc[i][j][1]),
                          "+f"(acc[i][j][2]), "+f"(acc[i][j][3])
                        : "r"(a[i][0]), "r"(a[i][1]), "r"(a[i][2]), "r"(a[i][3]),
                          "r"(bfr[j][0]), "r"(bfr[j][1]));
                }
        }
        __syncthreads();                       // buf free for reuse at it+3
    }

    // --- epilogue: signs into SB (aliases dead stage buffers) ---
    unsigned char* SB = reinterpret_cast<unsigned char*>(smem);  // 128x128
    const int qr = lane >> 2;        // 0..7
    const int qc = (lane & 3) * 2;   // 0,2,4,6
#pragma unroll
    for (int i = 0; i < 4; i++)
#pragma unroll
        for (int j = 0; j < 4; j++) {
            int row0 = wm + i * 16 + qr;
            int col0 = wn + j * 8 + qc;
            SB[row0 * 128 + col0]           = (acc[i][j][0] >= 0.0f) ? 1 : 0;
            SB[row0 * 128 + col0 + 1]       = (acc[i][j][1] >= 0.0f) ? 1 : 0;
            SB[(row0 + 8) * 128 + col0]     = (acc[i][j][2] >= 0.0f) ? 1 : 0;
            SB[(row0 + 8) * 128 + col0 + 1] = (acc[i][j][3] >= 0.0f) ? 1 : 0;
        }
    __syncthreads();

    // --- pack: 128 rows x 2 u64 words = 256 words, one per thread ---
    {
        int row  = tid >> 1;
        int half = tid & 1;
        unsigned long long bits = 0ULL;
#pragma unroll
        for (int j = 0; j < 64; j++)
            bits |= (unsigned long long)(SB[row * 128 + half * 64 + j] & 1) << j;
        g_encp[(size_t)(bm + row) * DQ + (bn >> 6) + half] = bits;
    }
}

// ---------------------------------------------------------------------------
// Kernel 2: pack classes_hv floats {0.0,1.0} -> bits.
// ---------------------------------------------------------------------------
__global__ void pack_hv_kernel(const float* __restrict__ HV)
{
    int w = blockIdx.x * blockDim.x + threadIdx.x;   // 0 .. C_DIM*DQ-1
    if (w >= C_DIM * DQ) return;
    int c = w >> 7;
    int q = w & 127;
    const float* base = HV + (size_t)c * D_DIM + (size_t)q * 64;
    unsigned long long bits = 0ULL;
#pragma unroll
    for (int j = 0; j < 64; j++)
        bits |= (unsigned long long)(base[j] > 0.5f ? 1 : 0) << j;
    g_hvp[w] = bits;
}

// ---------------------------------------------------------------------------
// Kernel 3: Hamming popcount GEMM (float output; values exact small ints).
// ---------------------------------------------------------------------------
__global__ __launch_bounds__(256)
void popc_gemm_kernel(float* __restrict__ OUT)
{
    __shared__ unsigned long long es[16][128];
    __shared__ unsigned long long hs[16][64];

    const int tid = threadIdx.x;
    const int tx = tid & 15;
    const int ty = tid >> 4;
    const int bm = blockIdx.y * 128;
    const int bn = blockIdx.x * 64;

    int acc[8][4];
#pragma unroll
    for (int i = 0; i < 8; i++)
#pragma unroll
        for (int j = 0; j < 4; j++) acc[i][j] = 0;

    for (int k0 = 0; k0 < DQ; k0 += 16) {
        for (int i = tid; i < 128 * 16; i += 256) {
            int row = i >> 4;
            int w   = i & 15;
            es[w][row] = g_encp[(size_t)(bm + row) * DQ + k0 + w];
        }
        for (int i = tid; i < 64 * 16; i += 256) {
            int row = i >> 4;
            int w   = i & 15;
            hs[w][row] = g_hvp[(size_t)(bn + row) * DQ + k0 + w];
        }
        __syncthreads();

#pragma unroll
        for (int w = 0; w < 16; w++) {
            unsigned long long h[4], e[8];
#pragma unroll
            for (int j = 0; j < 4; j++) h[j] = hs[w][tx * 4 + j];
#pragma unroll
            for (int i = 0; i < 8; i++) e[i] = es[w][ty * 8 + i];
#pragma unroll
            for (int i = 0; i < 8; i++)
#pragma unroll
                for (int j = 0; j < 4; j++)
                    acc[i][j] += __popcll(e[i] ^ h[j]);
        }
        __syncthreads();
    }

#pragma unroll
    for (int i = 0; i < 8; i++)
#pragma unroll
        for (int j = 0; j < 4; j++)
            OUT[(size_t)(bm + ty * 8 + i) * C_DIM + bn + tx * 4 + j] =
                (float)acc[i][j];
}

// ---------------------------------------------------------------------------
// Launch: prefill -> convert X,W -> HMMA GEMM+pack -> pack hv -> popc GEMM.
// ---------------------------------------------------------------------------
extern "C" void kernel_launch(void* const* d_in, const int* in_sizes, int n_in,
                              void* d_out, int out_size)
{
    const float* x  = (const float*)d_in[0];   // [8192, 1024]
    const float* W  = (const float*)d_in[1];   // [1024, 8192]
    const float* hv = (const float*)d_in[2];   // [512, 8192]
    float* out = (float*)d_out;                // [8192, 512] float32

    cudaFuncSetAttribute(gemm_mma_binpack_kernel,
                         cudaFuncAttributeMaxDynamicSharedMemorySize, SMEM_TOTAL);

    fill_out_kernel<<<(out_size + 255) / 256, 256>>>(out, out_size);

    convert_x_kernel<<<(B_DIM * F_DIM / 4 + 255) / 256, 256>>>(x);
    convert_w_kernel<<<(F_DIM * D_DIM / 4 + 255) / 256, 256>>>(W);

    dim3 g1(D_DIM / 128, B_DIM / 128);         // (64, 64)
    gemm_mma_binpack_kernel<<<g1, 256, SMEM_TOTAL>>>();

    pack_hv_kernel<<<(C_DIM * DQ + 255) / 256, 256>>>(hv);

    dim3 g3(C_DIM / 64, B_DIM / 128);          // (8, 64)
    popc_gemm_kernel<<<g3, 256>>>(out);
}

// round 11
// speedup vs baseline: 3.1882x; 1.1304x over previous
#include <cuda_runtime.h>
#include <cuda_bf16.h>
#include <cstdint>

// Problem sizes (fixed)
#define B_DIM 8192
#define F_DIM 1024
#define D_DIM 8192
#define C_DIM 512
#define KSPLIT (3 * F_DIM)   // 3072: [Xhi|Xhi|Xlo] x [Whi;Wlo;Whi]
#define NK    (KSPLIT / 32)  // 96 BK=32 steps for GEMM1
#define NK2   (D_DIM / 64)   // 128 BK=64 steps for IMMA

// Static device scratch (no allocation)
__device__ __nv_bfloat16 g_Xs[(size_t)B_DIM * KSPLIT];    // 48 MB split X
__device__ __nv_bfloat16 g_Ws[(size_t)KSPLIT * D_DIM];    // 48 MB split W
__device__ signed char   g_enc8[(size_t)B_DIM * D_DIM];   // 64 MB enc {0,1} bytes
__device__ signed char   g_hv8[(size_t)C_DIM * D_DIM];    // 4 MB hv' {+1,-1}
__device__ int           g_rsh[C_DIM];                    // rowsum_h per class

union BF2U { __nv_bfloat16 b; unsigned short u; };
__device__ __forceinline__ unsigned short bf_bits(float f) {
    BF2U t; t.b = __float2bfloat16_rn(f); return t.u;
}

__device__ __forceinline__ void cpa16(uint32_t dst, const void* src) {
    asm volatile("cp.async.cg.shared.global [%0], [%1], 16;"
                 :: "r"(dst), "l"(src) : "memory");
}
#define CP_COMMIT() asm volatile("cp.async.commit_group;" ::: "memory")
#define CP_WAIT1()  asm volatile("cp.async.wait_group 1;"  ::: "memory")

// GEMM1 smem stage: A 128x40 bf16 = 10240 B, B 32x136 bf16 = 8704 B
#define A_BYTES 10240
#define STAGE_BYTES 18944
#define SMEM_TOTAL (3 * STAGE_BYTES)       // 56832
// IMMA smem stage: A 128x(64+16pad) s8 = 10240 B, B same
#define A2_BYTES 10240
#define STAGE2_BYTES 20480
#define SMEM2_TOTAL (3 * STAGE2_BYTES)     // 61440

// ---------------------------------------------------------------------------
// Kernel 0 (diagnostic prefill)
// ---------------------------------------------------------------------------
__global__ void fill_out_kernel(float* __restrict__ out, int n)
{
    int i = blockIdx.x * blockDim.x + threadIdx.x;
    if (i < n) out[i] = 4096.0f;
}

// ---------------------------------------------------------------------------
// Convert X[B,F] fp32 -> Xs[B,3K] bf16 as [hi | hi | lo].
// ---------------------------------------------------------------------------
__global__ void convert_x_kernel(const float* __restrict__ X)
{
    int idx = blockIdx.x * blockDim.x + threadIdx.x;
    if (idx >= B_DIM * F_DIM / 4) return;
    int b = idx >> 8;
    int f = (idx & 255) * 4;
    float4 v = *reinterpret_cast<const float4*>(&X[(size_t)b * F_DIM + f]);

    unsigned short h[4], l[4];
    float vv[4] = {v.x, v.y, v.z, v.w};
#pragma unroll
    for (int i = 0; i < 4; i++) {
        h[i] = bf_bits(vv[i]);
        BF2U t; t.u = h[i];
        l[i] = bf_bits(vv[i] - __bfloat162float(t.b));
    }
    uint2 hw = make_uint2((unsigned)h[0] | ((unsigned)h[1] << 16),
                          (unsigned)h[2] | ((unsigned)h[3] << 16));
    uint2 lw = make_uint2((unsigned)l[0] | ((unsigned)l[1] << 16),
                          (unsigned)l[2] | ((unsigned)l[3] << 16));
    size_t base = (size_t)b * KSPLIT;
    *reinterpret_cast<uint2*>(&g_Xs[base + f])              = hw;
    *reinterpret_cast<uint2*>(&g_Xs[base + F_DIM + f])      = hw;
    *reinterpret_cast<uint2*>(&g_Xs[base + 2 * F_DIM + f])  = lw;
}

// ---------------------------------------------------------------------------
// Convert W[F,D] fp32 -> Ws[3K,D] bf16 as [hi ; lo ; hi].
// ---------------------------------------------------------------------------
__global__ void convert_w_kernel(const float* __restrict__ W)
{
    int idx = blockIdx.x * blockDim.x + threadIdx.x;
    if (idx >= F_DIM * D_DIM / 4) return;
    int f = idx >> 11;
    int d = (idx & 2047) * 4;
    float4 v = *reinterpret_cast<const float4*>(&W[(size_t)f * D_DIM + d]);

    unsigned short h[4], l[4];
    float vv[4] = {v.x, v.y, v.z, v.w};
#pragma unroll
    for (int i = 0; i < 4; i++) {
        h[i] = bf_bits(vv[i]);
        BF2U t; t.u = h[i];
        l[i] = bf_bits(vv[i] - __bfloat162float(t.b));
    }
    uint2 hw = make_uint2((unsigned)h[0] | ((unsigned)h[1] << 16),
                          (unsigned)h[2] | ((unsigned)h[3] << 16));
    uint2 lw = make_uint2((unsigned)l[0] | ((unsigned)l[1] << 16),
                          (unsigned)l[2] | ((unsigned)l[3] << 16));
    *reinterpret_cast<uint2*>(&g_Ws[(size_t)f * D_DIM + d])               = hw;
    *reinterpret_cast<uint2*>(&g_Ws[(size_t)(F_DIM + f) * D_DIM + d])     = lw;
    *reinterpret_cast<uint2*>(&g_Ws[(size_t)(2 * F_DIM + f) * D_DIM + d]) = hw;
}

// ---------------------------------------------------------------------------
// Kernel 1: bf16 HMMA GEMM  Xs[B,3K] @ Ws[3K,D], fp32 accum.
// Epilogue: sign -> {0,1} s8 bytes -> g_enc8. (inner loop identical to R10)
// ---------------------------------------------------------------------------
__global__ __launch_bounds__(256, 2)
void gemm_mma_binpack_kernel()
{
    extern __shared__ __align__(16) char smem[];

    const int tid  = threadIdx.x;
    const int wid  = tid >> 5;
    const int lane = tid & 31;
    const int bm = blockIdx.y * 128;
    const int bn = blockIdx.x * 128;

    const int wm = (wid >> 2) * 64;
    const int wn = (wid & 3) * 32;

    float acc[4][4][4];
#pragma unroll
    for (int i = 0; i < 4; i++)
#pragma unroll
        for (int j = 0; j < 4; j++)
#pragma unroll
            for (int r = 0; r < 4; r++) acc[i][j][r] = 0.0f;

    const int lg = lane >> 3;
    const int lr = lane & 7;

    uint32_t smem_u32_base;
    asm("{ .reg .u64 t; cvta.to.shared.u64 t, %1; cvt.u32.u64 %0, t; }"
        : "=r"(smem_u32_base) : "l"(smem));

    auto load_stage = [&](int kt, int buf) {
        const uint32_t ab = smem_u32_base + buf * STAGE_BYTES;
        const uint32_t bb = ab + A_BYTES;
#pragma unroll
        for (int u = 0; u < 2; u++) {
            int idx = tid + u * 256;
            int row = idx >> 2;
            int ch  = idx & 3;
            cpa16(ab + row * 80 + ch * 16,
                  &g_Xs[(size_t)(bm + row) * KSPLIT + kt + ch * 8]);
        }
#pragma unroll
        for (int u = 0; u < 2; u++) {
            int idx = tid + u * 256;
            int kr = idx >> 4;
            int ch = idx & 15;
            cpa16(bb + kr * 272 + ch * 16,
                  &g_Ws[(size_t)(kt + kr) * D_DIM + bn + ch * 8]);
        }
    };

    load_stage(0, 0);  CP_COMMIT();
    load_stage(32, 1); CP_COMMIT();

    for (int it = 0; it < NK; it++) {
        CP_WAIT1();
        __syncthreads();

        if (it + 2 < NK) load_stage((it + 2) * 32, (it + 2) % 3);
        CP_COMMIT();

        const int buf = it % 3;
        __nv_bfloat16 (*As)[40] =
            reinterpret_cast<__nv_bfloat16(*)[40]>(smem + buf * STAGE_BYTES);
        __nv_bfloat16 (*Bs)[136] =
            reinterpret_cast<__nv_bfloat16(*)[136]>(smem + buf * STAGE_BYTES + A_BYTES);

#pragma unroll
        for (int kk = 0; kk < 32; kk += 16) {
            unsigned a[4][4];
#pragma unroll
            for (int i = 0; i < 4; i++) {
                int row = wm + i * 16 + lr + (lg & 1) * 8;
                int col = kk + (lg >> 1) * 8;
                unsigned addr = (unsigned)__cvta_generic_to_shared(&As[row][col]);
                asm volatile(
                    "ldmatrix.sync.aligned.m8n8.x4.shared.b16 {%0,%1,%2,%3}, [%4];"
                    : "=r"(a[i][0]), "=r"(a[i][1]), "=r"(a[i][2]), "=r"(a[i][3])
                    : "r"(addr));
            }
            unsigned bfr[4][2];
#pragma unroll
            for (int j = 0; j < 2; j++) {
                int krow = kk + lr + (lg & 1) * 8;
                int col  = wn + j * 16 + (lg >> 1) * 8;
                unsigned addr = (unsigned)__cvta_generic_to_shared(&Bs[krow][col]);
                unsigned r0, r1, r2, r3;
                asm volatile(
                    "ldmatrix.sync.aligned.m8n8.x4.trans.shared.b16 {%0,%1,%2,%3}, [%4];"
                    : "=r"(r0), "=r"(r1), "=r"(r2), "=r"(r3)
                    : "r"(addr));
                bfr[j * 2 + 0][0] = r0; bfr[j * 2 + 0][1] = r1;
                bfr[j * 2 + 1][0] = r2; bfr[j * 2 + 1][1] = r3;
            }
#pragma unroll
            for (int i = 0; i < 4; i++)
#pragma unroll
                for (int j = 0; j < 4; j++) {
                    asm volatile(
                        "mma.sync.aligned.m16n8k16.row.col.f32.bf16.bf16.f32 "
                        "{%0,%1,%2,%3}, {%4,%5,%6,%7}, {%8,%9}, {%0,%1,%2,%3};"
                        : "+f"(acc[i][j][0]), "+f"(acc[i][j][1]),
                          "+f"(acc[i][j][2]), "+f"(acc[i][j][3])
                        : "r"(a[i][0]), "r"(a[i][1]), "r"(a[i][2]), "r"(a[i][3]),
                          "r"(bfr[j][0]), "r"(bfr[j][1]));
                }
        }
        __syncthreads();
    }

    // --- epilogue: signs -> SB bytes -> g_enc8 (s8 {0,1}) ---
    unsigned char* SB = reinterpret_cast<unsigned char*>(smem);  // 128x128
    const int qr = lane >> 2;
    const int qc = (lane & 3) * 2;
#pragma unroll
    for (int i = 0; i < 4; i++)
#pragma unroll
        for (int j = 0; j < 4; j++) {
            int row0 = wm + i * 16 + qr;
            int col0 = wn + j * 8 + qc;
            SB[row0 * 128 + col0]           = (acc[i][j][0] >= 0.0f) ? 1 : 0;
            SB[row0 * 128 + col0 + 1]       = (acc[i][j][1] >= 0.0f) ? 1 : 0;
            SB[(row0 + 8) * 128 + col0]     = (acc[i][j][2] >= 0.0f) ? 1 : 0;
            SB[(row0 + 8) * 128 + col0 + 1] = (acc[i][j][3] >= 0.0f) ? 1 : 0;
        }
    __syncthreads();

    // vectorized copy SB -> g_enc8: 1024 x 16B chunks, 4 per thread
#pragma unroll
    for (int u = 0; u < 4; u++) {
        int idx = tid + u * 256;
        int row = idx >> 3;
        int ch  = idx & 7;
        uint4 v = *reinterpret_cast<const uint4*>(SB + row * 128 + ch * 16);
        *reinterpret_cast<uint4*>(
            &g_enc8[(size_t)(bm + row) * D_DIM + bn + ch * 16]) = v;
    }
}

// ---------------------------------------------------------------------------
// Kernel 2: classes_hv {0,1} floats -> hv' = 1-2h in s8, plus rowsum_h[c].
// One block per class.
// ---------------------------------------------------------------------------
__global__ void convert_hv_kernel(const float* __restrict__ HV)
{
    __shared__ int red[256];
    const int c   = blockIdx.x;
    const int tid = threadIdx.x;
    int sum = 0;
#pragma unroll
    for (int it = 0; it < 8; it++) {
        int d = (it * 256 + tid) * 4;
        float4 f = *reinterpret_cast<const float4*>(&HV[(size_t)c * D_DIM + d]);
        int h0 = f.x > 0.5f, h1 = f.y > 0.5f, h2 = f.z > 0.5f, h3 = f.w > 0.5f;
        sum += h0 + h1 + h2 + h3;
        char4 v;
        v.x = (char)(1 - 2 * h0); v.y = (char)(1 - 2 * h1);
        v.z = (char)(1 - 2 * h2); v.w = (char)(1 - 2 * h3);
        *reinterpret_cast<char4*>(&g_hv8[(size_t)c * D_DIM + d]) = v;
    }
    red[tid] = sum;
    __syncthreads();
    for (int s = 128; s > 0; s >>= 1) {
        if (tid < s) red[tid] += red[tid + s];
        __syncthreads();
    }
    if (tid == 0) g_rsh[c] = red[0];
}

// ---------------------------------------------------------------------------
// Kernel 3: s8 IMMA GEMM  enc8[B,D] @ hv8[C,D]^T  (dot'), epilogue adds
// rowsum_h[c] -> resp as float. 128x128 tile, BK=64, m16n8k32 s8.
// resp[b,c] = (sum e) - 2(sum e*h) + (sum h) = dot' + rsh[c]   (exact int)
// ---------------------------------------------------------------------------
__global__ __launch_bounds__(256, 2)
void imma_resp_kernel(float* __restrict__ OUT)
{
    extern __shared__ __align__(16) char smem[];

    const int tid  = threadIdx.x;
    const int wid  = tid >> 5;
    const int lane = tid & 31;
    const int bm = blockIdx.y * 128;
    const int bn = blockIdx.x * 128;

    const int wm = (wid >> 2) * 64;
    const int wn = (wid & 3) * 32;

    int acc[4][4][4];
#pragma unroll
    for (int i = 0; i < 4; i++)
#pragma unroll
        for (int j = 0; j < 4; j++)
#pragma unroll
            for (int r = 0; r < 4; r++) acc[i][j][r] = 0;

    const int lg = lane >> 3;
    const int lr = lane & 7;

    uint32_t smem_u32_base;
    asm("{ .reg .u64 t; cvta.to.shared.u64 t, %1; cvt.u32.u64 %0, t; }"
        : "=r"(smem_u32_base) : "l"(smem));

    // stage: A 128 rows x 64 s8 (+16 pad) = 80B rows; B same (rows = n)
    auto load_stage = [&](int kt, int buf) {
        const uint32_t ab = smem_u32_base + buf * STAGE2_BYTES;
        const uint32_t bb = ab + A2_BYTES;
#pragma unroll
        for (int u = 0; u < 2; u++) {
            int idx = tid + u * 256;
            int row = idx >> 2;
            int ch  = idx & 3;
            cpa16(ab + row * 80 + ch * 16,
                  &g_enc8[(size_t)(bm + row) * D_DIM + kt + ch * 16]);
        }
#pragma unroll
        for (int u = 0; u < 2; u++) {
            int idx = tid + u * 256;
            int row = idx >> 2;
            int ch  = idx & 3;
            cpa16(bb + row * 80 + ch * 16,
                  &g_hv8[(size_t)(bn + row) * D_DIM + kt + ch * 16]);
        }
    };

    load_stage(0, 0);  CP_COMMIT();
    load_stage(64, 1); CP_COMMIT();

    for (int it = 0; it < NK2; it++) {
        CP_WAIT1();
        __syncthreads();

        if (it + 2 < NK2) load_stage((it + 2) * 64, (it + 2) % 3);
        CP_COMMIT();

        const char* As = smem + (it % 3) * STAGE2_BYTES;
        const char* Bs = As + A2_BYTES;

#pragma unroll
        for (int kkb = 0; kkb < 64; kkb += 32) {
            // A fragments: 4 m-frags, ldmatrix x4 (b16 view of s8 k32)
            unsigned a[4][4];
#pragma unroll
            for (int i = 0; i < 4; i++) {
                int row = wm + i * 16 + lr + (lg & 1) * 8;
                int col = kkb + (lg >> 1) * 16;        // byte offset
                unsigned addr =
                    (unsigned)__cvta_generic_to_shared(As + row * 80 + col);
                asm volatile(
                    "ldmatrix.sync.aligned.m8n8.x4.shared.b16 {%0,%1,%2,%3}, [%4];"
                    : "=r"(a[i][0]), "=r"(a[i][1]), "=r"(a[i][2]), "=r"(a[i][3])
                    : "r"(addr));
            }
            // B fragments: rows are n (col-major B); no trans needed.
            // x4 tiles: (n0-7,k0-15)(n0-7,k16-31)(n8-15,k0-15)(n8-15,k16-31)
            unsigned bfr[4][2];
#pragma unroll
            for (int j = 0; j < 2; j++) {
                int row = wn + j * 16 + lr + (lg >> 1) * 8;
                int col = kkb + (lg & 1) * 16;
                unsigned addr =
                    (unsigned)__cvta_generic_to_shared(Bs + row * 80 + col);
                unsigned r0, r1, r2, r3;
                asm volatile(
                    "ldmatrix.sync.aligned.m8n8.x4.shared.b16 {%0,%1,%2,%3}, [%4];"
                    : "=r"(r0), "=r"(r1), "=r"(r2), "=r"(r3)
                    : "r"(addr));
                bfr[j * 2 + 0][0] = r0; bfr[j * 2 + 0][1] = r1;
                bfr[j * 2 + 1][0] = r2; bfr[j * 2 + 1][1] = r3;
            }
#pragma unroll
            for (int i = 0; i < 4; i++)
#pragma unroll
                for (int j = 0; j < 4; j++) {
                    asm volatile(
                        "mma.sync.aligned.m16n8k32.row.col.s32.s8.s8.s32 "
                        "{%0,%1,%2,%3}, {%4,%5,%6,%7}, {%8,%9}, {%0,%1,%2,%3};"
                        : "+r"(acc[i][j][0]), "+r"(acc[i][j][1]),
                          "+r"(acc[i][j][2]), "+r"(acc[i][j][3])
                        : "r"(a[i][0]), "r"(a[i][1]), "r"(a[i][2]), "r"(a[i][3]),
                          "r"(bfr[j][0]), "r"(bfr[j][1]));
                }
        }
        __syncthreads();
    }

    // --- epilogue: resp = acc + rsh[col], store float ---
    const int qr = lane >> 2;
    const int qc = (lane & 3) * 2;
#pragma unroll
    for (int i = 0; i < 4; i++)
#pragma unroll
        for (int j = 0; j < 4; j++) {
            int row0 = bm + wm + i * 16 + qr;
            int col0 = bn + wn + j * 8 + qc;
            int r0 = g_rsh[col0];
            int r1 = g_rsh[col0 + 1];
            OUT[(size_t)row0 * C_DIM + col0]           = (float)(acc[i][j][0] + r0);
            OUT[(size_t)row0 * C_DIM + col0 + 1]       = (float)(acc[i][j][1] + r1);
            OUT[(size_t)(row0 + 8) * C_DIM + col0]     = (float)(acc[i][j][2] + r0);
            OUT[(size_t)(row0 + 8) * C_DIM + col0 + 1] = (float)(acc[i][j][3] + r1);
        }
}

// ---------------------------------------------------------------------------
// Launch: prefill -> convert X,W -> GEMM1(sign bytes) -> convert hv -> IMMA.
// ---------------------------------------------------------------------------
extern "C" void kernel_launch(void* const* d_in, const int* in_sizes, int n_in,
                              void* d_out, int out_size)
{
    const float* x  = (const float*)d_in[0];   // [8192, 1024]
    const float* W  = (const float*)d_in[1];   // [1024, 8192]
    const float* hv = (const float*)d_in[2];   // [512, 8192]
    float* out = (float*)d_out;                // [8192, 512] float32

    cudaFuncSetAttribute(gemm_mma_binpack_kernel,
                         cudaFuncAttributeMaxDynamicSharedMemorySize, SMEM_TOTAL);
    cudaFuncSetAttribute(imma_resp_kernel,
                         cudaFuncAttributeMaxDynamicSharedMemorySize, SMEM2_TOTAL);

    fill_out_kernel<<<(out_size + 255) / 256, 256>>>(out, out_size);

    convert_x_kernel<<<(B_DIM * F_DIM / 4 + 255) / 256, 256>>>(x);
    convert_w_kernel<<<(F_DIM * D_DIM / 4 + 255) / 256, 256>>>(W);

    dim3 g1(D_DIM / 128, B_DIM / 128);         // (64, 64)
    gemm_mma_binpack_kernel<<<g1, 256, SMEM_TOTAL>>>();

    convert_hv_kernel<<<C_DIM, 256>>>(hv);

    dim3 g3(C_DIM / 128, B_DIM / 128);         // (4, 64)
    imma_resp_kernel<<<g3, 256, SMEM2_TOTAL>>>(out);
}

// round 12
// speedup vs baseline: 3.7217x; 1.1673x over previous
#include <cuda_runtime.h>
#include <cuda_fp16.h>
#include <cstdint>

// Problem sizes (fixed)
#define B_DIM 8192
#define F_DIM 1024
#define D_DIM 8192
#define C_DIM 512
#define KSPLIT 2048          // [Xhi|Xlo] x [Wh;Wh]  (fp16 2-term split)
#define NK1   (KSPLIT / 32)  // 64 BK=32 steps for GEMM1
#define NK2   (D_DIM / 64)   // 128 BK=64 steps for IMMA

// Static device scratch (no allocation)
__device__ __half      g_Xs[(size_t)B_DIM * KSPLIT];    // 32 MB split X [hi|lo]
__device__ __half      g_Wh[(size_t)F_DIM * D_DIM];     // 16 MB W hi (single copy)
__device__ signed char g_enc8[(size_t)B_DIM * D_DIM];   // 64 MB enc {0,1} bytes
__device__ signed char g_hv8[(size_t)C_DIM * D_DIM];    // 4 MB hv' {+1,-1}
__device__ int         g_rsh[C_DIM];                    // rowsum_h per class

__device__ __forceinline__ void cpa16(uint32_t dst, const void* src) {
    asm volatile("cp.async.cg.shared.global [%0], [%1], 16;"
                 :: "r"(dst), "l"(src) : "memory");
}
#define CP_COMMIT() asm volatile("cp.async.commit_group;" ::: "memory")
#define CP_WAIT1()  asm volatile("cp.async.wait_group 1;"  ::: "memory")

// GEMM1 smem stage: A 128x(32+8) fp16 = 10240 B; B 32x(256+8) fp16 = 16896 B
#define A_BYTES 10240
#define STAGE_BYTES 27136
#define SMEM_TOTAL (3 * STAGE_BYTES)       // 81408
// IMMA smem stage: A 128x(64+16pad) s8 = 10240 B, B same
#define A2_BYTES 10240
#define STAGE2_BYTES 20480
#define SMEM2_TOTAL (3 * STAGE2_BYTES)     // 61440

// ---------------------------------------------------------------------------
// Kernel 0 (diagnostic prefill)
// ---------------------------------------------------------------------------
__global__ void fill_out_kernel(float* __restrict__ out, int n)
{
    int i = blockIdx.x * blockDim.x + threadIdx.x;
    if (i < n) out[i] = 4096.0f;
}

// ---------------------------------------------------------------------------
// Convert X[B,F] fp32 -> Xs[B,2K] fp16 as [hi | lo] (x = hi + lo to 2^-22).
// ---------------------------------------------------------------------------
__global__ void convert_x_kernel(const float* __restrict__ X)
{
    int idx = blockIdx.x * blockDim.x + threadIdx.x;
    if (idx >= B_DIM * F_DIM / 4) return;
    int b = idx >> 8;
    int f = (idx & 255) * 4;
    float4 v = *reinterpret_cast<const float4*>(&X[(size_t)b * F_DIM + f]);

    unsigned short h[4], l[4];
    float vv[4] = {v.x, v.y, v.z, v.w};
#pragma unroll
    for (int i = 0; i < 4; i++) {
        __half hh = __float2half_rn(vv[i]);
        __half ll = __float2half_rn(vv[i] - __half2float(hh));
        h[i] = __half_as_ushort(hh);
        l[i] = __half_as_ushort(ll);
    }
    uint2 hw = make_uint2((unsigned)h[0] | ((unsigned)h[1] << 16),
                          (unsigned)h[2] | ((unsigned)h[3] << 16));
    uint2 lw = make_uint2((unsigned)l[0] | ((unsigned)l[1] << 16),
                          (unsigned)l[2] | ((unsigned)l[3] << 16));
    size_t base = (size_t)b * KSPLIT;
    *reinterpret_cast<uint2*>(&g_Xs[base + f])         = hw;
    *reinterpret_cast<uint2*>(&g_Xs[base + F_DIM + f]) = lw;
}

// ---------------------------------------------------------------------------
// Convert W[F,D] fp32 -> Wh[F,D] fp16 (hi only; reused for both K segments).
// ---------------------------------------------------------------------------
__global__ void convert_w_kernel(const float* __restrict__ W)
{
    int idx = blockIdx.x * blockDim.x + threadIdx.x;
    if (idx >= F_DIM * D_DIM / 4) return;
    int f = idx >> 11;
    int d = (idx & 2047) * 4;
    float4 v = *reinterpret_cast<const float4*>(&W[(size_t)f * D_DIM + d]);
    unsigned short h0 = __half_as_ushort(__float2half_rn(v.x));
    unsigned short h1 = __half_as_ushort(__float2half_rn(v.y));
    unsigned short h2 = __half_as_ushort(__float2half_rn(v.z));
    unsigned short h3 = __half_as_ushort(__float2half_rn(v.w));
    uint2 hw = make_uint2((unsigned)h0 | ((unsigned)h1 << 16),
                          (unsigned)h2 | ((unsigned)h3 << 16));
    *reinterpret_cast<uint2*>(&g_Wh[(size_t)f * D_DIM + d]) = hw;
}

// ---------------------------------------------------------------------------
// Kernel 1: fp16 HMMA GEMM  Xs[B,2K] @ [Wh;Wh], fp32 accum.
// CTA tile 128x256, 256 threads (8 warps as 2x4), warp tile 64x64, BK=32.
// 3-stage cp.async pipeline. Epilogue: sign -> {0,1} s8 bytes -> g_enc8.
// ---------------------------------------------------------------------------
__global__ __launch_bounds__(256, 1)
void gemm_mma_binpack_kernel()
{
    extern __shared__ __align__(16) char smem[];

    const int tid  = threadIdx.x;
    const int wid  = tid >> 5;
    const int lane = tid & 31;
    const int bm = blockIdx.y * 128;
    const int bn = blockIdx.x * 256;

    const int wm = (wid >> 2) * 64;   // 0 or 64
    const int wn = (wid & 3) * 64;    // 0,64,128,192

    float acc[4][8][4];
#pragma unroll
    for (int i = 0; i < 4; i++)
#pragma unroll
        for (int j = 0; j < 8; j++)
#pragma unroll
            for (int r = 0; r < 4; r++) acc[i][j][r] = 0.0f;

    const int lg = lane >> 3;
    const int lr = lane & 7;

    uint32_t smem_u32_base;
    asm("{ .reg .u64 t; cvta.to.shared.u64 t, %1; cvt.u32.u64 %0, t; }"
        : "=r"(smem_u32_base) : "l"(smem));

    auto load_stage = [&](int kt, int buf) {
        const uint32_t ab = smem_u32_base + buf * STAGE_BYTES;
        const uint32_t bb = ab + A_BYTES;
        const int kw = (kt < F_DIM) ? kt : (kt - F_DIM);   // W segment fold
        // A: 128 rows x 32 halfs = 512 x 16B chunks, 2/thread
#pragma unroll
        for (int u = 0; u < 2; u++) {
            int idx = tid + u * 256;
            int row = idx >> 2;
            int ch  = idx & 3;
            cpa16(ab + row * 80 + ch * 16,
                  &g_Xs[(size_t)(bm + row) * KSPLIT + kt + ch * 8]);
        }
        // B: 32 rows x 256 halfs = 1024 x 16B chunks, 4/thread
#pragma unroll
        for (int u = 0; u < 4; u++) {
            int idx = tid + u * 256;
            int kr = idx >> 5;
            int ch = idx & 31;
            cpa16(bb + kr * 528 + ch * 16,
                  &g_Wh[(size_t)(kw + kr) * D_DIM + bn + ch * 8]);
        }
    };

    load_stage(0, 0);  CP_COMMIT();
    load_stage(32, 1); CP_COMMIT();

    for (int it = 0; it < NK1; it++) {
        CP_WAIT1();
        __syncthreads();

        if (it + 2 < NK1) load_stage((it + 2) * 32, (it + 2) % 3);
        CP_COMMIT();

        const char* As = smem + (it % 3) * STAGE_BYTES;
        const char* Bs = As + A_BYTES;

#pragma unroll
        for (int kk = 0; kk < 32; kk += 16) {
            unsigned a[4][4];
#pragma unroll
            for (int i = 0; i < 4; i++) {
                int row = wm + i * 16 + lr + (lg & 1) * 8;
                int col = kk + (lg >> 1) * 8;
                unsigned addr = (unsigned)__cvta_generic_to_shared(
                    As + row * 80 + col * 2);
                asm volatile(
                    "ldmatrix.sync.aligned.m8n8.x4.shared.b16 {%0,%1,%2,%3}, [%4];"
                    : "=r"(a[i][0]), "=r"(a[i][1]), "=r"(a[i][2]), "=r"(a[i][3])
                    : "r"(addr));
            }
            unsigned bfr[8][2];
#pragma unroll
            for (int j = 0; j < 4; j++) {
                int krow = kk + lr + (lg & 1) * 8;
                int col  = wn + j * 16 + (lg >> 1) * 8;
                unsigned addr = (unsigned)__cvta_generic_to_shared(
                    Bs + krow * 528 + col * 2);
                unsigned r0, r1, r2, r3;
                asm volatile(
                    "ldmatrix.sync.aligned.m8n8.x4.trans.shared.b16 {%0,%1,%2,%3}, [%4];"
                    : "=r"(r0), "=r"(r1), "=r"(r2), "=r"(r3)
                    : "r"(addr));
                bfr[j * 2 + 0][0] = r0; bfr[j * 2 + 0][1] = r1;
                bfr[j * 2 + 1][0] = r2; bfr[j * 2 + 1][1] = r3;
            }
#pragma unroll
            for (int i = 0; i < 4; i++)
#pragma unroll
                for (int j = 0; j < 8; j++) {
                    asm volatile(
                        "mma.sync.aligned.m16n8k16.row.col.f32.f16.f16.f32 "
                        "{%0,%1,%2,%3}, {%4,%5,%6,%7}, {%8,%9}, {%0,%1,%2,%3};"
                        : "+f"(acc[i][j][0]), "+f"(acc[i][j][1]),
                          "+f"(acc[i][j][2]), "+f"(acc[i][j][3])
                        : "r"(a[i][0]), "r"(a[i][1]), "r"(a[i][2]), "r"(a[i][3]),
                          "r"(bfr[j][0]), "r"(bfr[j][1]));
                }
        }
        __syncthreads();
    }

    // --- epilogue: signs -> SB bytes (128x256, aliases stage buffers) ---
    unsigned char* SB = reinterpret_cast<unsigned char*>(smem);
    const int qr = lane >> 2;
    const int qc = (lane & 3) * 2;
#pragma unroll
    for (int i = 0; i < 4; i++)
#pragma unroll
        for (int j = 0; j < 8; j++) {
            int row0 = wm + i * 16 + qr;
            int col0 = wn + j * 8 + qc;
            SB[row0 * 256 + col0]           = (acc[i][j][0] >= 0.0f) ? 1 : 0;
            SB[row0 * 256 + col0 + 1]       = (acc[i][j][1] >= 0.0f) ? 1 : 0;
            SB[(row0 + 8) * 256 + col0]     = (acc[i][j][2] >= 0.0f) ? 1 : 0;
            SB[(row0 + 8) * 256 + col0 + 1] = (acc[i][j][3] >= 0.0f) ? 1 : 0;
        }
    __syncthreads();

    // vectorized copy SB -> g_enc8: 2048 x 16B chunks, 8 per thread
#pragma unroll
    for (int u = 0; u < 8; u++) {
        int idx = tid + u * 256;
        int row = idx >> 4;
        int ch  = idx & 15;
        uint4 v = *reinterpret_cast<const uint4*>(SB + row * 256 + ch * 16);
        *reinterpret_cast<uint4*>(
            &g_enc8[(size_t)(bm + row) * D_DIM + bn + ch * 16]) = v;
    }
}

// ---------------------------------------------------------------------------
// Kernel 2: classes_hv {0,1} floats -> hv' = 1-2h in s8, plus rowsum_h[c].
// ---------------------------------------------------------------------------
__global__ void convert_hv_kernel(const float* __restrict__ HV)
{
    __shared__ int red[256];
    const int c   = blockIdx.x;
    const int tid = threadIdx.x;
    int sum = 0;
#pragma unroll
    for (int it = 0; it < 8; it++) {
        int d = (it * 256 + tid) * 4;
        float4 f = *reinterpret_cast<const float4*>(&HV[(size_t)c * D_DIM + d]);
        int h0 = f.x > 0.5f, h1 = f.y > 0.5f, h2 = f.z > 0.5f, h3 = f.w > 0.5f;
        sum += h0 + h1 + h2 + h3;
        char4 v;
        v.x = (char)(1 - 2 * h0); v.y = (char)(1 - 2 * h1);
        v.z = (char)(1 - 2 * h2); v.w = (char)(1 - 2 * h3);
        *reinterpret_cast<char4*>(&g_hv8[(size_t)c * D_DIM + d]) = v;
    }
    red[tid] = sum;
    __syncthreads();
    for (int s = 128; s > 0; s >>= 1) {
        if (tid < s) red[tid] += red[tid + s];
        __syncthreads();
    }
    if (tid == 0) g_rsh[c] = red[0];
}

// ---------------------------------------------------------------------------
// Kernel 3: s8 IMMA GEMM  enc8[B,D] @ hv8[C,D]^T, + rowsum_h[c] -> float out.
// (unchanged from R11 — verified)
// ---------------------------------------------------------------------------
__global__ __launch_bounds__(256, 2)
void imma_resp_kernel(float* __restrict__ OUT)
{
    extern __shared__ __align__(16) char smem[];

    const int tid  = threadIdx.x;
    const int wid  = tid >> 5;
    const int lane = tid & 31;
    const int bm = blockIdx.y * 128;
    const int bn = blockIdx.x * 128;

    const int wm = (wid >> 2) * 64;
    const int wn = (wid & 3) * 32;

    int acc[4][4][4];
#pragma unroll
    for (int i = 0; i < 4; i++)
#pragma unroll
        for (int j = 0; j < 4; j++)
#pragma unroll
            for (int r = 0; r < 4; r++) acc[i][j][r] = 0;

    const int lg = lane >> 3;
    const int lr = lane & 7;

    uint32_t smem_u32_base;
    asm("{ .reg .u64 t; cvta.to.shared.u64 t, %1; cvt.u32.u64 %0, t; }"
        : "=r"(smem_u32_base) : "l"(smem));

    auto load_stage = [&](int kt, int buf) {
        const uint32_t ab = smem_u32_base + buf * STAGE2_BYTES;
        const uint32_t bb = ab + A2_BYTES;
#pragma unroll
        for (int u = 0; u < 2; u++) {
            int idx = tid + u * 256;
            int row = idx >> 2;
            int ch  = idx & 3;
            cpa16(ab + row * 80 + ch * 16,
                  &g_enc8[(size_t)(bm + row) * D_DIM + kt + ch * 16]);
        }
#pragma unroll
        for (int u = 0; u < 2; u++) {
            int idx = tid + u * 256;
            int row = idx >> 2;
            int ch  = idx & 3;
            cpa16(bb + row * 80 + ch * 16,
                  &g_hv8[(size_t)(bn + row) * D_DIM + kt + ch * 16]);
        }
    };

    load_stage(0, 0);  CP_COMMIT();
    load_stage(64, 1); CP_COMMIT();

    for (int it = 0; it < NK2; it++) {
        CP_WAIT1();
        __syncthreads();

        if (it + 2 < NK2) load_stage((it + 2) * 64, (it + 2) % 3);
        CP_COMMIT();

        const char* As = smem + (it % 3) * STAGE2_BYTES;
        const char* Bs = As + A2_BYTES;

#pragma unroll
        for (int kkb = 0; kkb < 64; kkb += 32) {
            unsigned a[4][4];
#pragma unroll
            for (int i = 0; i < 4; i++) {
                int row = wm + i * 16 + lr + (lg & 1) * 8;
                int col = kkb + (lg >> 1) * 16;
                unsigned addr =
                    (unsigned)__cvta_generic_to_shared(As + row * 80 + col);
                asm volatile(
                    "ldmatrix.sync.aligned.m8n8.x4.shared.b16 {%0,%1,%2,%3}, [%4];"
                    : "=r"(a[i][0]), "=r"(a[i][1]), "=r"(a[i][2]), "=r"(a[i][3])
                    : "r"(addr));
            }
            unsigned bfr[4][2];
#pragma unroll
            for (int j = 0; j < 2; j++) {
                int row = wn + j * 16 + lr + (lg >> 1) * 8;
                int col = kkb + (lg & 1) * 16;
                unsigned addr =
                    (unsigned)__cvta_generic_to_shared(Bs + row * 80 + col);
                unsigned r0, r1, r2, r3;
                asm volatile(
                    "ldmatrix.sync.aligned.m8n8.x4.shared.b16 {%0,%1,%2,%3}, [%4];"
                    : "=r"(r0), "=r"(r1), "=r"(r2), "=r"(r3)
                    : "r"(addr));
                bfr[j * 2 + 0][0] = r0; bfr[j * 2 + 0][1] = r1;
                bfr[j * 2 + 1][0] = r2; bfr[j * 2 + 1][1] = r3;
            }
#pragma unroll
            for (int i = 0; i < 4; i++)
#pragma unroll
                for (int j = 0; j < 4; j++) {
                    asm volatile(
                        "mma.sync.aligned.m16n8k32.row.col.s32.s8.s8.s32 "
                        "{%0,%1,%2,%3}, {%4,%5,%6,%7}, {%8,%9}, {%0,%1,%2,%3};"
                        : "+r"(acc[i][j][0]), "+r"(acc[i][j][1]),
                          "+r"(acc[i][j][2]), "+r"(acc[i][j][3])
                        : "r"(a[i][0]), "r"(a[i][1]), "r"(a[i][2]), "r"(a[i][3]),
                          "r"(bfr[j][0]), "r"(bfr[j][1]));
                }
        }
        __syncthreads();
    }

    const int qr = lane >> 2;
    const int qc = (lane & 3) * 2;
#pragma unroll
    for (int i = 0; i < 4; i++)
#pragma unroll
        for (int j = 0; j < 4; j++) {
            int row0 = bm + wm + i * 16 + qr;
            int col0 = bn + wn + j * 8 + qc;
            int r0 = g_rsh[col0];
            int r1 = g_rsh[col0 + 1];
            OUT[(size_t)row0 * C_DIM + col0]           = (float)(acc[i][j][0] + r0);
            OUT[(size_t)row0 * C_DIM + col0 + 1]       = (float)(acc[i][j][1] + r1);
            OUT[(size_t)(row0 + 8) * C_DIM + col0]     = (float)(acc[i][j][2] + r0);
            OUT[(size_t)(row0 + 8) * C_DIM + col0 + 1] = (float)(acc[i][j][3] + r1);
        }
}

// ---------------------------------------------------------------------------
// Launch: prefill -> convert X,W -> GEMM1(sign bytes) -> convert hv -> IMMA.
// ---------------------------------------------------------------------------
extern "C" void kernel_launch(void* const* d_in, const int* in_sizes, int n_in,
                              void* d_out, int out_size)
{
    const float* x  = (const float*)d_in[0];   // [8192, 1024]
    const float* W  = (const float*)d_in[1];   // [1024, 8192]
    const float* hv = (const float*)d_in[2];   // [512, 8192]
    float* out = (float*)d_out;                // [8192, 512] float32

    cudaFuncSetAttribute(gemm_mma_binpack_kernel,
                         cudaFuncAttributeMaxDynamicSharedMemorySize, SMEM_TOTAL);
    cudaFuncSetAttribute(imma_resp_kernel,
                         cudaFuncAttributeMaxDynamicSharedMemorySize, SMEM2_TOTAL);

    fill_out_kernel<<<(out_size + 255) / 256, 256>>>(out, out_size);

    convert_x_kernel<<<(B_DIM * F_DIM / 4 + 255) / 256, 256>>>(x);
    convert_w_kernel<<<(F_DIM * D_DIM / 4 + 255) / 256, 256>>>(W);

    dim3 g1(D_DIM / 256, B_DIM / 128);         // (32, 64)
    gemm_mma_binpack_kernel<<<g1, 256, SMEM_TOTAL>>>();

    convert_hv_kernel<<<C_DIM, 256>>>(hv);

    dim3 g3(C_DIM / 128, B_DIM / 128);         // (4, 64)
    imma_resp_kernel<<<g3, 256, SMEM2_TOTAL>>>(out);
}

// round 13
// speedup vs baseline: 4.3842x; 1.1780x over previous
#include <cuda_runtime.h>
#include <cuda_fp16.h>
#include <cstdint>

// Problem sizes (fixed)
#define B_DIM 8192
#define F_DIM 1024
#define D_DIM 8192
#define C_DIM 512
#define KSPLIT 2048          // [Xhi|Xlo] x [Wh;Wh]  (fp16 2-term split)
#define NK1   (KSPLIT / 32)  // 64 BK=32 steps for GEMM1
#define NK2   (D_DIM / 64)   // 128 BK=64 steps for IMMA

// Static device scratch (no allocation)
__device__ __half      g_Xs[(size_t)B_DIM * KSPLIT];    // 32 MB split X [hi|lo]
__device__ __half      g_Wh[(size_t)F_DIM * D_DIM];     // 16 MB W hi (single copy)
__device__ signed char g_enc8[(size_t)B_DIM * D_DIM];   // 64 MB enc {0,1} bytes
__device__ signed char g_hv8[(size_t)C_DIM * D_DIM];    // 4 MB hv' {+1,-1}
__device__ int         g_rsh[C_DIM];                    // rowsum_h per class

__device__ __forceinline__ void cpa16(uint32_t dst, const void* src) {
    asm volatile("cp.async.cg.shared.global [%0], [%1], 16;"
                 :: "r"(dst), "l"(src) : "memory");
}
#define CP_COMMIT() asm volatile("cp.async.commit_group;" ::: "memory")
#define CP_WAIT1()  asm volatile("cp.async.wait_group 1;"  ::: "memory")

// GEMM1 smem stage (R11 geometry): A 128x40 fp16 = 10240 B, B 32x136 fp16 = 8704 B
#define A_BYTES 10240
#define STAGE_BYTES 18944
#define SMEM_TOTAL (3 * STAGE_BYTES)       // 56832
// IMMA smem stage: A 128x(64+16pad) s8 = 10240 B, B same
#define A2_BYTES 10240
#define STAGE2_BYTES 20480
#define SMEM2_TOTAL (3 * STAGE2_BYTES)     // 61440

// ---------------------------------------------------------------------------
// Kernel 0 (diagnostic prefill)
// ---------------------------------------------------------------------------
__global__ void fill_out_kernel(float* __restrict__ out, int n)
{
    int i = blockIdx.x * blockDim.x + threadIdx.x;
    if (i < n) out[i] = 4096.0f;
}

// ---------------------------------------------------------------------------
// Convert X[B,F] fp32 -> Xs[B,2K] fp16 as [hi | lo] (x = hi + lo to 2^-22).
// ---------------------------------------------------------------------------
__global__ void convert_x_kernel(const float* __restrict__ X)
{
    int idx = blockIdx.x * blockDim.x + threadIdx.x;
    if (idx >= B_DIM * F_DIM / 4) return;
    int b = idx >> 8;
    int f = (idx & 255) * 4;
    float4 v = *reinterpret_cast<const float4*>(&X[(size_t)b * F_DIM + f]);

    unsigned short h[4], l[4];
    float vv[4] = {v.x, v.y, v.z, v.w};
#pragma unroll
    for (int i = 0; i < 4; i++) {
        __half hh = __float2half_rn(vv[i]);
        __half ll = __float2half_rn(vv[i] - __half2float(hh));
        h[i] = __half_as_ushort(hh);
        l[i] = __half_as_ushort(ll);
    }
    uint2 hw = make_uint2((unsigned)h[0] | ((unsigned)h[1] << 16),
                          (unsigned)h[2] | ((unsigned)h[3] << 16));
    uint2 lw = make_uint2((unsigned)l[0] | ((unsigned)l[1] << 16),
                          (unsigned)l[2] | ((unsigned)l[3] << 16));
    size_t base = (size_t)b * KSPLIT;
    *reinterpret_cast<uint2*>(&g_Xs[base + f])         = hw;
    *reinterpret_cast<uint2*>(&g_Xs[base + F_DIM + f]) = lw;
}

// ---------------------------------------------------------------------------
// Convert W[F,D] fp32 -> Wh[F,D] fp16 (hi only; reused for both K segments).
// ---------------------------------------------------------------------------
__global__ void convert_w_kernel(const float* __restrict__ W)
{
    int idx = blockIdx.x * blockDim.x + threadIdx.x;
    if (idx >= F_DIM * D_DIM / 4) return;
    int f = idx >> 11;
    int d = (idx & 2047) * 4;
    float4 v = *reinterpret_cast<const float4*>(&W[(size_t)f * D_DIM + d]);
    unsigned short h0 = __half_as_ushort(__float2half_rn(v.x));
    unsigned short h1 = __half_as_ushort(__float2half_rn(v.y));
    unsigned short h2 = __half_as_ushort(__float2half_rn(v.z));
    unsigned short h3 = __half_as_ushort(__float2half_rn(v.w));
    uint2 hw = make_uint2((unsigned)h0 | ((unsigned)h1 << 16),
                          (unsigned)h2 | ((unsigned)h3 << 16));
    *reinterpret_cast<uint2*>(&g_Wh[(size_t)f * D_DIM + d]) = hw;
}

// ---------------------------------------------------------------------------
// Kernel 1: fp16 HMMA GEMM  Xs[B,2K] @ [Wh;Wh], fp32 accum, fused sign->s8.
// R11 geometry: CTA 128x128, 256 threads (8 warps 2x4), warp 64x32, BK=32,
// 3-stage cp.async pipeline, 2 CTAs/SM.
// ---------------------------------------------------------------------------
__global__ __launch_bounds__(256, 2)
void gemm_mma_binpack_kernel()
{
    extern __shared__ __align__(16) char smem[];

    const int tid  = threadIdx.x;
    const int wid  = tid >> 5;
    const int lane = tid & 31;
    const int bm = blockIdx.y * 128;
    const int bn = blockIdx.x * 128;

    const int wm = (wid >> 2) * 64;   // 0 or 64
    const int wn = (wid & 3) * 32;    // 0,32,64,96

    float acc[4][4][4];
#pragma unroll
    for (int i = 0; i < 4; i++)
#pragma unroll
        for (int j = 0; j < 4; j++)
#pragma unroll
            for (int r = 0; r < 4; r++) acc[i][j][r] = 0.0f;

    const int lg = lane >> 3;
    const int lr = lane & 7;

    uint32_t smem_u32_base;
    asm("{ .reg .u64 t; cvta.to.shared.u64 t, %1; cvt.u32.u64 %0, t; }"
        : "=r"(smem_u32_base) : "l"(smem));

    auto load_stage = [&](int kt, int buf) {
        const uint32_t ab = smem_u32_base + buf * STAGE_BYTES;
        const uint32_t bb = ab + A_BYTES;
        const int kw = (kt < F_DIM) ? kt : (kt - F_DIM);   // W segment fold
        // A: 128 rows x 32 halfs = 512 x 16B chunks, 2/thread
#pragma unroll
        for (int u = 0; u < 2; u++) {
            int idx = tid + u * 256;
            int row = idx >> 2;
            int ch  = idx & 3;
            cpa16(ab + row * 80 + ch * 16,
                  &g_Xs[(size_t)(bm + row) * KSPLIT + kt + ch * 8]);
        }
        // B: 32 rows x 128 halfs = 512 x 16B chunks, 2/thread
#pragma unroll
        for (int u = 0; u < 2; u++) {
            int idx = tid + u * 256;
            int kr = idx >> 4;
            int ch = idx & 15;
            cpa16(bb + kr * 272 + ch * 16,
                  &g_Wh[(size_t)(kw + kr) * D_DIM + bn + ch * 8]);
        }
    };

    load_stage(0, 0);  CP_COMMIT();
    load_stage(32, 1); CP_COMMIT();

    for (int it = 0; it < NK1; it++) {
        CP_WAIT1();
        __syncthreads();

        if (it + 2 < NK1) load_stage((it + 2) * 32, (it + 2) % 3);
        CP_COMMIT();

        const char* As = smem + (it % 3) * STAGE_BYTES;
        const char* Bs = As + A_BYTES;

#pragma unroll
        for (int kk = 0; kk < 32; kk += 16) {
            unsigned a[4][4];
#pragma unroll
            for (int i = 0; i < 4; i++) {
                int row = wm + i * 16 + lr + (lg & 1) * 8;
                int col = kk + (lg >> 1) * 8;
                unsigned addr = (unsigned)__cvta_generic_to_shared(
                    As + row * 80 + col * 2);
                asm volatile(
                    "ldmatrix.sync.aligned.m8n8.x4.shared.b16 {%0,%1,%2,%3}, [%4];"
                    : "=r"(a[i][0]), "=r"(a[i][1]), "=r"(a[i][2]), "=r"(a[i][3])
                    : "r"(addr));
            }
            unsigned bfr[4][2];
#pragma unroll
            for (int j = 0; j < 2; j++) {
                int krow = kk + lr + (lg & 1) * 8;
                int col  = wn + j * 16 + (lg >> 1) * 8;
                unsigned addr = (unsigned)__cvta_generic_to_shared(
                    Bs + krow * 272 + col * 2);
                unsigned r0, r1, r2, r3;
                asm volatile(
                    "ldmatrix.sync.aligned.m8n8.x4.trans.shared.b16 {%0,%1,%2,%3}, [%4];"
                    : "=r"(r0), "=r"(r1), "=r"(r2), "=r"(r3)
                    : "r"(addr));
                bfr[j * 2 + 0][0] = r0; bfr[j * 2 + 0][1] = r1;
                bfr[j * 2 + 1][0] = r2; bfr[j * 2 + 1][1] = r3;
            }
#pragma unroll
            for (int i = 0; i < 4; i++)
#pragma unroll
                for (int j = 0; j < 4; j++) {
                    asm volatile(
                        "mma.sync.aligned.m16n8k16.row.col.f32.f16.f16.f32 "
                        "{%0,%1,%2,%3}, {%4,%5,%6,%7}, {%8,%9}, {%0,%1,%2,%3};"
                        : "+f"(acc[i][j][0]), "+f"(acc[i][j][1]),
                          "+f"(acc[i][j][2]), "+f"(acc[i][j][3])
                        : "r"(a[i][0]), "r"(a[i][1]), "r"(a[i][2]), "r"(a[i][3]),
                          "r"(bfr[j][0]), "r"(bfr[j][1]));
                }
        }
        __syncthreads();
    }

    // --- epilogue: signs -> SB bytes (128x128, aliases stage buffers) ---
    unsigned char* SB = reinterpret_cast<unsigned char*>(smem);
    const int qr = lane >> 2;
    const int qc = (lane & 3) * 2;
#pragma unroll
    for (int i = 0; i < 4; i++)
#pragma unroll
        for (int j = 0; j < 4; j++) {
            int row0 = wm + i * 16 + qr;
            int col0 = wn + j * 8 + qc;
            SB[row0 * 128 + col0]           = (acc[i][j][0] >= 0.0f) ? 1 : 0;
            SB[row0 * 128 + col0 + 1]       = (acc[i][j][1] >= 0.0f) ? 1 : 0;
            SB[(row0 + 8) * 128 + col0]     = (acc[i][j][2] >= 0.0f) ? 1 : 0;
            SB[(row0 + 8) * 128 + col0 + 1] = (acc[i][j][3] >= 0.0f) ? 1 : 0;
        }
    __syncthreads();

    // vectorized copy SB -> g_enc8: 1024 x 16B chunks, 4 per thread
#pragma unroll
    for (int u = 0; u < 4; u++) {
        int idx = tid + u * 256;
        int row = idx >> 3;
        int ch  = idx & 7;
        uint4 v = *reinterpret_cast<const uint4*>(SB + row * 128 + ch * 16);
        *reinterpret_cast<uint4*>(
            &g_enc8[(size_t)(bm + row) * D_DIM + bn + ch * 16]) = v;
    }
}

// ---------------------------------------------------------------------------
// Kernel 2: classes_hv {0,1} floats -> hv' = 1-2h in s8, plus rowsum_h[c].
// ---------------------------------------------------------------------------
__global__ void convert_hv_kernel(const float* __restrict__ HV)
{
    __shared__ int red[256];
    const int c   = blockIdx.x;
    const int tid = threadIdx.x;
    int sum = 0;
#pragma unroll
    for (int it = 0; it < 8; it++) {
        int d = (it * 256 + tid) * 4;
        float4 f = *reinterpret_cast<const float4*>(&HV[(size_t)c * D_DIM + d]);
        int h0 = f.x > 0.5f, h1 = f.y > 0.5f, h2 = f.z > 0.5f, h3 = f.w > 0.5f;
        sum += h0 + h1 + h2 + h3;
        char4 v;
        v.x = (char)(1 - 2 * h0); v.y = (char)(1 - 2 * h1);
        v.z = (char)(1 - 2 * h2); v.w = (char)(1 - 2 * h3);
        *reinterpret_cast<char4*>(&g_hv8[(size_t)c * D_DIM + d]) = v;
    }
    red[tid] = sum;
    __syncthreads();
    for (int s = 128; s > 0; s >>= 1) {
        if (tid < s) red[tid] += red[tid + s];
        __syncthreads();
    }
    if (tid == 0) g_rsh[c] = red[0];
}

// ---------------------------------------------------------------------------
// Kernel 3: s8 IMMA GEMM  enc8[B,D] @ hv8[C,D]^T, + rowsum_h[c] -> float out.
// (unchanged — verified in R11/R12)
// ---------------------------------------------------------------------------
__global__ __launch_bounds__(256, 2)
void imma_resp_kernel(float* __restrict__ OUT)
{
    extern __shared__ __align__(16) char smem[];

    const int tid  = threadIdx.x;
    const int wid  = tid >> 5;
    const int lane = tid & 31;
    const int bm = blockIdx.y * 128;
    const int bn = blockIdx.x * 128;

    const int wm = (wid >> 2) * 64;
    const int wn = (wid & 3) * 32;

    int acc[4][4][4];
#pragma unroll
    for (int i = 0; i < 4; i++)
#pragma unroll
        for (int j = 0; j < 4; j++)
#pragma unroll
            for (int r = 0; r < 4; r++) acc[i][j][r] = 0;

    const int lg = lane >> 3;
    const int lr = lane & 7;

    uint32_t smem_u32_base;
    asm("{ .reg .u64 t; cvta.to.shared.u64 t, %1; cvt.u32.u64 %0, t; }"
        : "=r"(smem_u32_base) : "l"(smem));

    auto load_stage = [&](int kt, int buf) {
        const uint32_t ab = smem_u32_base + buf * STAGE2_BYTES;
        const uint32_t bb = ab + A2_BYTES;
#pragma unroll
        for (int u = 0; u < 2; u++) {
            int idx = tid + u * 256;
            int row = idx >> 2;
            int ch  = idx & 3;
            cpa16(ab + row * 80 + ch * 16,
                  &g_enc8[(size_t)(bm + row) * D_DIM + kt + ch * 16]);
        }
#pragma unroll
        for (int u = 0; u < 2; u++) {
            int idx = tid + u * 256;
            int row = idx >> 2;
            int ch  = idx & 3;
            cpa16(bb + row * 80 + ch * 16,
                  &g_hv8[(size_t)(bn + row) * D_DIM + kt + ch * 16]);
        }
    };

    load_stage(0, 0);  CP_COMMIT();
    load_stage(64, 1); CP_COMMIT();

    for (int it = 0; it < NK2; it++) {
        CP_WAIT1();
        __syncthreads();

        if (it + 2 < NK2) load_stage((it + 2) * 64, (it + 2) % 3);
        CP_COMMIT();

        const char* As = smem + (it % 3) * STAGE2_BYTES;
        const char* Bs = As + A2_BYTES;

#pragma unroll
        for (int kkb = 0; kkb < 64; kkb += 32) {
            unsigned a[4][4];
#pragma unroll
            for (int i = 0; i < 4; i++) {
                int row = wm + i * 16 + lr + (lg & 1) * 8;
                int col = kkb + (lg >> 1) * 16;
                unsigned addr =
                    (unsigned)__cvta_generic_to_shared(As + row * 80 + col);
                asm volatile(
                    "ldmatrix.sync.aligned.m8n8.x4.shared.b16 {%0,%1,%2,%3}, [%4];"
                    : "=r"(a[i][0]), "=r"(a[i][1]), "=r"(a[i][2]), "=r"(a[i][3])
                    : "r"(addr));
            }
            unsigned bfr[4][2];
#pragma unroll
            for (int j = 0; j < 2; j++) {
                int row = wn + j * 16 + lr + (lg >> 1) * 8;
                int col = kkb + (lg & 1) * 16;
                unsigned addr =
                    (unsigned)__cvta_generic_to_shared(Bs + row * 80 + col);
                unsigned r0, r1, r2, r3;
                asm volatile(
                    "ldmatrix.sync.aligned.m8n8.x4.shared.b16 {%0,%1,%2,%3}, [%4];"
                    : "=r"(r0), "=r"(r1), "=r"(r2), "=r"(r3)
                    : "r"(addr));
                bfr[j * 2 + 0][0] = r0; bfr[j * 2 + 0][1] = r1;
                bfr[j * 2 + 1][0] = r2; bfr[j * 2 + 1][1] = r3;
            }
#pragma unroll
            for (int i = 0; i < 4; i++)
#pragma unroll
                for (int j = 0; j < 4; j++) {
                    asm volatile(
                        "mma.sync.aligned.m16n8k32.row.col.s32.s8.s8.s32 "
                        "{%0,%1,%2,%3}, {%4,%5,%6,%7}, {%8,%9}, {%0,%1,%2,%3};"
                        : "+r"(acc[i][j][0]), "+r"(acc[i][j][1]),
                          "+r"(acc[i][j][2]), "+r"(acc[i][j][3])
                        : "r"(a[i][0]), "r"(a[i][1]), "r"(a[i][2]), "r"(a[i][3]),
                          "r"(bfr[j][0]), "r"(bfr[j][1]));
                }
        }
        __syncthreads();
    }

    const int qr = lane >> 2;
    const int qc = (lane & 3) * 2;
#pragma unroll
    for (int i = 0; i < 4; i++)
#pragma unroll
        for (int j = 0; j < 4; j++) {
            int row0 = bm + wm + i * 16 + qr;
            int col0 = bn + wn + j * 8 + qc;
            int r0 = g_rsh[col0];
            int r1 = g_rsh[col0 + 1];
            OUT[(size_t)row0 * C_DIM + col0]           = (float)(acc[i][j][0] + r0);
            OUT[(size_t)row0 * C_DIM + col0 + 1]       = (float)(acc[i][j][1] + r1);
            OUT[(size_t)(row0 + 8) * C_DIM + col0]     = (float)(acc[i][j][2] + r0);
            OUT[(size_t)(row0 + 8) * C_DIM + col0 + 1] = (float)(acc[i][j][3] + r1);
        }
}

// ---------------------------------------------------------------------------
// Launch: prefill -> convert X,W -> GEMM1(sign bytes) -> convert hv -> IMMA.
// ---------------------------------------------------------------------------
extern "C" void kernel_launch(void* const* d_in, const int* in_sizes, int n_in,
                              void* d_out, int out_size)
{
    const float* x  = (const float*)d_in[0];   // [8192, 1024]
    const float* W  = (const float*)d_in[1];   // [1024, 8192]
    const float* hv = (const float*)d_in[2];   // [512, 8192]
    float* out = (float*)d_out;                // [8192, 512] float32

    cudaFuncSetAttribute(gemm_mma_binpack_kernel,
                         cudaFuncAttributeMaxDynamicSharedMemorySize, SMEM_TOTAL);
    cudaFuncSetAttribute(imma_resp_kernel,
                         cudaFuncAttributeMaxDynamicSharedMemorySize, SMEM2_TOTAL);

    fill_out_kernel<<<(out_size + 255) / 256, 256>>>(out, out_size);

    convert_x_kernel<<<(B_DIM * F_DIM / 4 + 255) / 256, 256>>>(x);
    convert_w_kernel<<<(F_DIM * D_DIM / 4 + 255) / 256, 256>>>(W);

    dim3 g1(D_DIM / 128, B_DIM / 128);         // (64, 64)
    gemm_mma_binpack_kernel<<<g1, 256, SMEM_TOTAL>>>();

    convert_hv_kernel<<<C_DIM, 256>>>(hv);

    dim3 g3(C_DIM / 128, B_DIM / 128);         // (4, 64)
    imma_resp_kernel<<<g3, 256, SMEM2_TOTAL>>>(out);
}

// round 15
// speedup vs baseline: 7.8843x; 1.7984x over previous
#include <cuda_runtime.h>
#include <cuda_fp16.h>
#include <cstdint>

// Problem sizes (fixed)
#define B_DIM 8192
#define F_DIM 1024
#define D_DIM 8192
#define C_DIM 512
#define K1    1024           // plain fp16 GEMM, no split (error budget allows)
#define NK1   (K1 / 32)      // 32 BK=32 steps for GEMM1
#define NK2   (D_DIM / 64)   // 128 BK=64 steps for IMMA

// Static device scratch (no allocation)
__device__ __half      g_Xh[(size_t)B_DIM * K1];        // 16 MB X fp16
__device__ __half      g_Wh[(size_t)F_DIM * D_DIM];     // 16 MB W fp16
__device__ signed char g_enc8[(size_t)B_DIM * D_DIM];   // 64 MB enc {0,1} bytes
__device__ signed char g_hv8[(size_t)C_DIM * D_DIM];    // 4 MB hv' {+1,-1}
__device__ int         g_rsh[C_DIM];                    // rowsum_h per class

__device__ __forceinline__ void cpa16(uint32_t dst, const void* src) {
    asm volatile("cp.async.cg.shared.global [%0], [%1], 16;"
                 :: "r"(dst), "l"(src) : "memory");
}
#define CP_COMMIT() asm volatile("cp.async.commit_group;" ::: "memory")
#define CP_WAIT1()  asm volatile("cp.async.wait_group 1;"  ::: "memory")

// GEMM1 smem stage: A 128x40 fp16 = 10240 B, B 32x136 fp16 = 8704 B
#define A_BYTES 10240
#define STAGE_BYTES 18944
#define SMEM_TOTAL (3 * STAGE_BYTES)       // 56832
// IMMA smem stage: A 128x(64+16pad) s8 = 10240 B, B same
#define A2_BYTES 10240
#define STAGE2_BYTES 20480
#define SMEM2_TOTAL (3 * STAGE2_BYTES)     // 61440

// ---------------------------------------------------------------------------
// Kernel 0 (diagnostic prefill)
// ---------------------------------------------------------------------------
__global__ void fill_out_kernel(float* __restrict__ out, int n)
{
    int i = blockIdx.x * blockDim.x + threadIdx.x;
    if (i < n) out[i] = 4096.0f;
}

// ---------------------------------------------------------------------------
// Convert X[B,F] fp32 -> fp16 (plain round).
// ---------------------------------------------------------------------------
__global__ void convert_x_kernel(const float* __restrict__ X)
{
    int idx = blockIdx.x * blockDim.x + threadIdx.x;
    if (idx >= B_DIM * F_DIM / 4) return;
    float4 v = *reinterpret_cast<const float4*>(&X[(size_t)idx * 4]);
    unsigned short h0 = __half_as_ushort(__float2half_rn(v.x));
    unsigned short h1 = __half_as_ushort(__float2half_rn(v.y));
    unsigned short h2 = __half_as_ushort(__float2half_rn(v.z));
    unsigned short h3 = __half_as_ushort(__float2half_rn(v.w));
    uint2 hw = make_uint2((unsigned)h0 | ((unsigned)h1 << 16),
                          (unsigned)h2 | ((unsigned)h3 << 16));
    *reinterpret_cast<uint2*>(&g_Xh[(size_t)idx * 4]) = hw;
}

// ---------------------------------------------------------------------------
// Convert W[F,D] fp32 -> fp16 (plain round).
// ---------------------------------------------------------------------------
__global__ void convert_w_kernel(const float* __restrict__ W)
{
    int idx = blockIdx.x * blockDim.x + threadIdx.x;
    if (idx >= F_DIM * D_DIM / 4) return;
    float4 v = *reinterpret_cast<const float4*>(&W[(size_t)idx * 4]);
    unsigned short h0 = __half_as_ushort(__float2half_rn(v.x));
    unsigned short h1 = __half_as_ushort(__float2half_rn(v.y));
    unsigned short h2 = __half_as_ushort(__float2half_rn(v.z));
    unsigned short h3 = __half_as_ushort(__float2half_rn(v.w));
    uint2 hw = make_uint2((unsigned)h0 | ((unsigned)h1 << 16),
                          (unsigned)h2 | ((unsigned)h3 << 16));
    *reinterpret_cast<uint2*>(&g_Wh[(size_t)idx * 4]) = hw;
}

// ---------------------------------------------------------------------------
// Kernel 1: fp16 HMMA GEMM  Xh[B,K1] @ Wh[K1,D], fp32 accum, fused sign->s8.
// R13-verified geometry: CTA 128x128, 256 threads (8 warps 2x4), warp 64x32,
// BK=32, 3-stage cp.async pipeline, 2 CTAs/SM.
// ---------------------------------------------------------------------------
__global__ __launch_bounds__(256, 2)
void gemm_mma_binpack_kernel()
{
    extern __shared__ __align__(16) char smem[];

    const int tid  = threadIdx.x;
    const int wid  = tid >> 5;
    const int lane = tid & 31;
    const int bm = blockIdx.y * 128;
    const int bn = blockIdx.x * 128;

    const int wm = (wid >> 2) * 64;   // 0 or 64
    const int wn = (wid & 3) * 32;    // 0,32,64,96

    float acc[4][4][4];
#pragma unroll
    for (int i = 0; i < 4; i++)
#pragma unroll
        for (int j = 0; j < 4; j++)
#pragma unroll
            for (int r = 0; r < 4; r++) acc[i][j][r] = 0.0f;

    const int lg = lane >> 3;
    const int lr = lane & 7;

    uint32_t smem_u32_base;
    asm("{ .reg .u64 t; cvta.to.shared.u64 t, %1; cvt.u32.u64 %0, t; }"
        : "=r"(smem_u32_base) : "l"(smem));

    auto load_stage = [&](int kt, int buf) {
        const uint32_t ab = smem_u32_base + buf * STAGE_BYTES;
        const uint32_t bb = ab + A_BYTES;
        // A: 128 rows x 32 halfs = 512 x 16B chunks, 2/thread
#pragma unroll
        for (int u = 0; u < 2; u++) {
            int idx = tid + u * 256;
            int row = idx >> 2;
            int ch  = idx & 3;
            cpa16(ab + row * 80 + ch * 16,
                  &g_Xh[(size_t)(bm + row) * K1 + kt + ch * 8]);
        }
        // B: 32 rows x 128 halfs = 512 x 16B chunks, 2/thread
#pragma unroll
        for (int u = 0; u < 2; u++) {
            int idx = tid + u * 256;
            int kr = idx >> 4;
            int ch = idx & 15;
            cpa16(bb + kr * 272 + ch * 16,
                  &g_Wh[(size_t)(kt + kr) * D_DIM + bn + ch * 8]);
        }
    };

    load_stage(0, 0);  CP_COMMIT();
    load_stage(32, 1); CP_COMMIT();

    for (int it = 0; it < NK1; it++) {
        CP_WAIT1();
        __syncthreads();

        if (it + 2 < NK1) load_stage((it + 2) * 32, (it + 2) % 3);
        CP_COMMIT();

        const char* As = smem + (it % 3) * STAGE_BYTES;
        const char* Bs = As + A_BYTES;

#pragma unroll
        for (int kk = 0; kk < 32; kk += 16) {
            unsigned a[4][4];
#pragma unroll
            for (int i = 0; i < 4; i++) {
                int row = wm + i * 16 + lr + (lg & 1) * 8;
                int col = kk + (lg >> 1) * 8;
                unsigned addr = (unsigned)__cvta_generic_to_shared(
                    As + row * 80 + col * 2);
                asm volatile(
                    "ldmatrix.sync.aligned.m8n8.x4.shared.b16 {%0,%1,%2,%3}, [%4];"
                    : "=r"(a[i][0]), "=r"(a[i][1]), "=r"(a[i][2]), "=r"(a[i][3])
                    : "r"(addr));
            }
            unsigned bfr[4][2];
#pragma unroll
            for (int j = 0; j < 2; j++) {
                int krow = kk + lr + (lg & 1) * 8;
                int col  = wn + j * 16 + (lg >> 1) * 8;
                unsigned addr = (unsigned)__cvta_generic_to_shared(
                    Bs + krow * 272 + col * 2);
                unsigned r0, r1, r2, r3;
                asm volatile(
                    "ldmatrix.sync.aligned.m8n8.x4.trans.shared.b16 {%0,%1,%2,%3}, [%4];"
                    : "=r"(r0), "=r"(r1), "=r"(r2), "=r"(r3)
                    : "r"(addr));
                bfr[j * 2 + 0][0] = r0; bfr[j * 2 + 0][1] = r1;
                bfr[j * 2 + 1][0] = r2; bfr[j * 2 + 1][1] = r3;
            }
#pragma unroll
            for (int i = 0; i < 4; i++)
#pragma unroll
                for (int j = 0; j < 4; j++) {
                    asm volatile(
                        "mma.sync.aligned.m16n8k16.row.col.f32.f16.f16.f32 "
                        "{%0,%1,%2,%3}, {%4,%5,%6,%7}, {%8,%9}, {%0,%1,%2,%3};"
                        : "+f"(acc[i][j][0]), "+f"(acc[i][j][1]),
                          "+f"(acc[i][j][2]), "+f"(acc[i][j][3])
                        : "r"(a[i][0]), "r"(a[i][1]), "r"(a[i][2]), "r"(a[i][3]),
                          "r"(bfr[j][0]), "r"(bfr[j][1]));
                }
        }
        __syncthreads();
    }

    // --- epilogue: signs -> SB bytes (128x128, aliases stage buffers) ---
    unsigned char* SB = reinterpret_cast<unsigned char*>(smem);
    const int qr = lane >> 2;
    const int qc = (lane & 3) * 2;
#pragma unroll
    for (int i = 0; i < 4; i++)
#pragma unroll
        for (int j = 0; j < 4; j++) {
            int row0 = wm + i * 16 + qr;
            int col0 = wn + j * 8 + qc;
            SB[row0 * 128 + col0]           = (acc[i][j][0] >= 0.0f) ? 1 : 0;
            SB[row0 * 128 + col0 + 1]       = (acc[i][j][1] >= 0.0f) ? 1 : 0;
            SB[(row0 + 8) * 128 + col0]     = (acc[i][j][2] >= 0.0f) ? 1 : 0;
            SB[(row0 + 8) * 128 + col0 + 1] = (acc[i][j][3] >= 0.0f) ? 1 : 0;
        }
    __syncthreads();

    // vectorized copy SB -> g_enc8: 1024 x 16B chunks, 4 per thread
#pragma unroll
    for (int u = 0; u < 4; u++) {
        int idx = tid + u * 256;
        int row = idx >> 3;
        int ch  = idx & 7;
        uint4 v = *reinterpret_cast<const uint4*>(SB + row * 128 + ch * 16);
        *reinterpret_cast<uint4*>(
            &g_enc8[(size_t)(bm + row) * D_DIM + bn + ch * 16]) = v;
    }
}

// ---------------------------------------------------------------------------
// Kernel 2: classes_hv {0,1} floats -> hv' = 1-2h in s8, plus rowsum_h[c].
// ---------------------------------------------------------------------------
__global__ void convert_hv_kernel(const float* __restrict__ HV)
{
    __shared__ int red[256];
    const int c   = blockIdx.x;
    const int tid = threadIdx.x;
    int sum = 0;
#pragma unroll
    for (int it = 0; it < 8; it++) {
        int d = (it * 256 + tid) * 4;
        float4 f = *reinterpret_cast<const float4*>(&HV[(size_t)c * D_DIM + d]);
        int h0 = f.x > 0.5f, h1 = f.y > 0.5f, h2 = f.z > 0.5f, h3 = f.w > 0.5f;
        sum += h0 + h1 + h2 + h3;
        char4 v;
        v.x = (char)(1 - 2 * h0); v.y = (char)(1 - 2 * h1);
        v.z = (char)(1 - 2 * h2); v.w = (char)(1 - 2 * h3);
        *reinterpret_cast<char4*>(&g_hv8[(size_t)c * D_DIM + d]) = v;
    }
    red[tid] = sum;
    __syncthreads();
    for (int s = 128; s > 0; s >>= 1) {
        if (tid < s) red[tid] += red[tid + s];
        __syncthreads();
    }
    if (tid == 0) g_rsh[c] = red[0];
}

// ---------------------------------------------------------------------------
// Kernel 3: s8 IMMA GEMM  enc8[B,D] @ hv8[C,D]^T, + rowsum_h[c] -> float out.
// (unchanged — verified R11-R13)
// ---------------------------------------------------------------------------
__global__ __launch_bounds__(256, 2)
void imma_resp_kernel(float* __restrict__ OUT)
{
    extern __shared__ __align__(16) char smem[];

    const int tid  = threadIdx.x;
    const int wid  = tid >> 5;
    const int lane = tid & 31;
    const int bm = blockIdx.y * 128;
    const int bn = blockIdx.x * 128;

    const int wm = (wid >> 2) * 64;
    const int wn = (wid & 3) * 32;

    int acc[4][4][4];
#pragma unroll
    for (int i = 0; i < 4; i++)
#pragma unroll
        for (int j = 0; j < 4; j++)
#pragma unroll
            for (int r = 0; r < 4; r++) acc[i][j][r] = 0;

    const int lg = lane >> 3;
    const int lr = lane & 7;

    uint32_t smem_u32_base;
    asm("{ .reg .u64 t; cvta.to.shared.u64 t, %1; cvt.u32.u64 %0, t; }"
        : "=r"(smem_u32_base) : "l"(smem));

    auto load_stage = [&](int kt, int buf) {
        const uint32_t ab = smem_u32_base + buf * STAGE2_BYTES;
        const uint32_t bb = ab + A2_BYTES;
#pragma unroll
        for (int u = 0; u < 2; u++) {
            int idx = tid + u * 256;
            int row = idx >> 2;
            int ch  = idx & 3;
            cpa16(ab + row * 80 + ch * 16,
                  &g_enc8[(size_t)(bm + row) * D_DIM + kt + ch * 16]);
        }
#pragma unroll
        for (int u = 0; u < 2; u++) {
            int idx = tid + u * 256;
            int row = idx >> 2;
            int ch  = idx & 3;
            cpa16(bb + row * 80 + ch * 16,
                  &g_hv8[(size_t)(bn + row) * D_DIM + kt + ch * 16]);
        }
    };

    load_stage(0, 0);  CP_COMMIT();
    load_stage(64, 1); CP_COMMIT();

    for (int it = 0; it < NK2; it++) {
        CP_WAIT1();
        __syncthreads();

        if (it + 2 < NK2) load_stage((it + 2) * 64, (it + 2) % 3);
        CP_COMMIT();

        const char* As = smem + (it % 3) * STAGE2_BYTES;
        const char* Bs = As + A2_BYTES;

#pragma unroll
        for (int kkb = 0; kkb < 64; kkb += 32) {
            unsigned a[4][4];
#pragma unroll
            for (int i = 0; i < 4; i++) {
                int row = wm + i * 16 + lr + (lg & 1) * 8;
                int col = kkb + (lg >> 1) * 16;
                unsigned addr =
                    (unsigned)__cvta_generic_to_shared(As + row * 80 + col);
                asm volatile(
                    "ldmatrix.sync.aligned.m8n8.x4.shared.b16 {%0,%1,%2,%3}, [%4];"
                    : "=r"(a[i][0]), "=r"(a[i][1]), "=r"(a[i][2]), "=r"(a[i][3])
                    : "r"(addr));
            }
            unsigned bfr[4][2];
#pragma unroll
            for (int j = 0; j < 2; j++) {
                int row = wn + j * 16 + lr + (lg >> 1) * 8;
                int col = kkb + (lg & 1) * 16;
                unsigned addr =
                    (unsigned)__cvta_generic_to_shared(Bs + row * 80 + col);
                unsigned r0, r1, r2, r3;
                asm volatile(
                    "ldmatrix.sync.aligned.m8n8.x4.shared.b16 {%0,%1,%2,%3}, [%4];"
                    : "=r"(r0), "=r"(r1), "=r"(r2), "=r"(r3)
                    : "r"(addr));
                bfr[j * 2 + 0][0] = r0; bfr[j * 2 + 0][1] = r1;
                bfr[j * 2 + 1][0] = r2; bfr[j * 2 + 1][1] = r3;
            }
#pragma unroll
            for (int i = 0; i < 4; i++)
#pragma unroll
                for (int j = 0; j < 4; j++) {
                    asm volatile(
                        "mma.sync.aligned.m16n8k32.row.col.s32.s8.s8.s32 "
                        "{%0,%1,%2,%3}, {%4,%5,%6,%7}, {%8,%9}, {%0,%1,%2,%3};"
                        : "+r"(acc[i][j][0]), "+r"(acc[i][j][1]),
                          "+r"(acc[i][j][2]), "+r"(acc[i][j][3])
                        : "r"(a[i][0]), "r"(a[i][1]), "r"(a[i][2]), "r"(a[i][3]),
                          "r"(bfr[j][0]), "r"(bfr[j][1]));
                }
        }
        __syncthreads();
    }

    const int qr = lane >> 2;
    const int qc = (lane & 3) * 2;
#pragma unroll
    for (int i = 0; i < 4; i++)
#pragma unroll
        for (int j = 0; j < 4; j++) {
            int row0 = bm + wm + i * 16 + qr;
            int col0 = bn + wn + j * 8 + qc;
            int r0 = g_rsh[col0];
            int r1 = g_rsh[col0 + 1];
            OUT[(size_t)row0 * C_DIM + col0]           = (float)(acc[i][j][0] + r0);
            OUT[(size_t)row0 * C_DIM + col0 + 1]       = (float)(acc[i][j][1] + r1);
            OUT[(size_t)(row0 + 8) * C_DIM + col0]     = (float)(acc[i][j][2] + r0);
            OUT[(size_t)(row0 + 8) * C_DIM + col0 + 1] = (float)(acc[i][j][3] + r1);
        }
}

// ---------------------------------------------------------------------------
// Launch: prefill -> convert X,W -> GEMM1(sign bytes) -> convert hv -> IMMA.
// ---------------------------------------------------------------------------
extern "C" void kernel_launch(void* const* d_in, const int* in_sizes, int n_in,
                              void* d_out, int out_size)
{
    const float* x  = (const float*)d_in[0];   // [8192, 1024]
    const float* W  = (const float*)d_in[1];   // [1024, 8192]
    const float* hv = (const float*)d_in[2];   // [512, 8192]
    float* out = (float*)d_out;                // [8192, 512] float32

    cudaFuncSetAttribute(gemm_mma_binpack_kernel,
                         cudaFuncAttributeMaxDynamicSharedMemorySize, SMEM_TOTAL);
    cudaFuncSetAttribute(imma_resp_kernel,
                         cudaFuncAttributeMaxDynamicSharedMemorySize, SMEM2_TOTAL);

    fill_out_kernel<<<(out_size + 255) / 256, 256>>>(out, out_size);

    convert_x_kernel<<<(B_DIM * F_DIM / 4 + 255) / 256, 256>>>(x);
    convert_w_kernel<<<(F_DIM * D_DIM / 4 + 255) / 256, 256>>>(W);

    dim3 g1(D_DIM / 128, B_DIM / 128);         // (64, 64)
    gemm_mma_binpack_kernel<<<g1, 256, SMEM_TOTAL>>>();

    convert_hv_kernel<<<C_DIM, 256>>>(hv);

    dim3 g3(C_DIM / 128, B_DIM / 128);         // (4, 64)
    imma_resp_kernel<<<g3, 256, SMEM2_TOTAL>>>(out);
}